// round 11
// baseline (speedup 1.0000x reference)
#include <cuda_runtime.h>
#include <math.h>

#define BN 256
#define LL 8
#define EPSV 1e-3f

typedef unsigned long long ull;

__device__ __forceinline__ ull pack2(float a, float b){
  ull r; asm("mov.b64 %0,{%1,%2};" : "=l"(r) : "f"(a), "f"(b)); return r;
}
__device__ __forceinline__ ull dup2(float a){
  ull r; asm("mov.b64 %0,{%1,%1};" : "=l"(r) : "f"(a)); return r;
}
__device__ __forceinline__ void fma2(ull &d, ull a, ull b){
  asm("fma.rn.f32x2 %0,%1,%2,%0;" : "+l"(d) : "l"(a), "l"(b));
}
__device__ __forceinline__ float fsum2(ull v){
  float lo, hi; asm("mov.b64 {%0,%1},%2;" : "=f"(lo), "=f"(hi) : "l"(v)); return lo + hi;
}
__device__ __forceinline__ float2 unpk(ull v){
  float lo, hi; asm("mov.b64 {%0,%1},%2;" : "=f"(lo), "=f"(hi) : "l"(v)); return make_float2(lo, hi);
}
__device__ __forceinline__ float wred32(float v){
  v += __shfl_xor_sync(~0u, v, 16); v += __shfl_xor_sync(~0u, v, 8);
  v += __shfl_xor_sync(~0u, v, 4);  v += __shfl_xor_sync(~0u, v, 2);
  v += __shfl_xor_sync(~0u, v, 1);  return v;
}

__device__ float g_last[BN][64][64];
__device__ float g_cc[BN][100][64];
__device__ float g_d0[BN][64][64];
__device__ float g_d0T[BN][64][64];
__device__ float g_fbT[BN][2][64][64];   // [b][dir][f][t]  (transposed: row j=dir*64+f contiguous in t)
__device__ float g_mstate[BN][LL][2][64];
__device__ float g_states[BN][LL][2][64];
__device__ float g_byp[LL][BN][64][64];

__global__ void k_init(const float* __restrict__ x, const float* __restrict__ state){
  int b = blockIdx.x;
  for (int idx = threadIdx.x; idx < 64*80; idx += blockDim.x){
    int p = idx/80, c = idx%80;
    if (c < 64) g_last[b][p][c] = x[b*5120 + idx];
  }
  for (int idx = threadIdx.x; idx < 1024; idx += blockDim.x){
    int cp = idx >> 6, f = idx & 63;
    g_mstate[b][cp>>1][cp&1][f] = state[b*1024 + idx] + x[b*5120 + f*80 + 64 + cp];
  }
}

// ---------------- conv (f32x2 packed) ----------------
template<int NP>
__device__ __forceinline__ void tapN(const float* __restrict__ W, const float* __restrict__ xb,
                                     const int* ip, int oc, ull* a){
  #pragma unroll 2
  for (int c4 = 0; c4 < 16; c4++){
    float4 xv[NP];
    #pragma unroll
    for (int p = 0; p < NP; p++) xv[p] = *(const float4*)(xb + ip[p]*64 + c4*4);
    #pragma unroll
    for (int cc = 0; cc < 4; cc++){
      ulonglong2 w2 = *(const ulonglong2*)(W + (c4*4+cc)*64 + oc);
      #pragma unroll
      for (int p = 0; p < NP; p++){
        float x1 = (cc==0)?xv[p].x:(cc==1)?xv[p].y:(cc==2)?xv[p].z:xv[p].w;
        ull xx = dup2(x1);
        fma2(a[2*p], xx, w2.x);
        fma2(a[2*p+1], xx, w2.y);
      }
    }
  }
}

__device__ __forceinline__ float4 fin4(ull a0, ull a1, const float* bp){
  float2 p01 = unpk(a0), p23 = unpk(a1);
  return make_float4(p01.x + bp[0], p01.y + bp[1], p23.x + bp[2], p23.y + bp[3]);
}

__global__ void __launch_bounds__(256) k_conv(int layer,
                       const float* __restrict__ w4, const float* __restrict__ w3,
                       const float* __restrict__ w2, const float* __restrict__ w1,
                       const float* __restrict__ cb){
  __shared__ float xs[2][64][64];
  int b0 = blockIdx.x * 2;
  for (int idx = threadIdx.x; idx < 8192; idx += 256){
    int bb = idx >> 12, r = idx & 4095;
    (&xs[bb][0][0])[r] = (&g_last[b0+bb][0][0])[r];
  }
  __syncthreads();
  int lane = threadIdx.x & 31, wid = threadIdx.x >> 5;
  int bsel = lane >> 4, oc = (lane & 15)*4;
  const float* xb = &xs[bsel][0][0];
  int b = b0 + bsel;
  const float* W4 = w4 + (size_t)layer*262144;
  const float* W3 = w3 + (size_t)layer*110592;
  const float* W2 = w2 + (size_t)layer*32768;
  const float* W1 = w1 + (size_t)layer*4096;
  const float* CB = cb + layer*256;

  if (wid <= 4){
    if (wid == 0){
      ull a[2] = {0ull, 0ull};
      for (int t = 0; t < 64; t++){ int ip[1] = {t}; tapN<1>(W4 + t*4096, xb, ip, oc, a); }
      *(float4*)&g_cc[b][0][oc] = fin4(a[0], a[1], CB + oc);
    } else {
      int po = (wid-1)*2;
      int oz = po>>2, oy = (po>>1)&1;
      ull ac[4] = {0,0,0,0};
      for (int kz=0;kz<3;kz++) for(int ky=0;ky<3;ky++) for(int kx=0;kx<3;kx++){
        int base = ((oz+kz)*4 + oy+ky)*4 + kx;
        int ip[2] = {base, base+1};
        tapN<2>(W3 + ((kz*3+ky)*3+kx)*4096, xb, ip, oc, ac);
      }
      #pragma unroll
      for (int p = 0; p < 2; p++)
        *(float4*)&g_cc[b][1+po+p][oc] = fin4(ac[2*p], ac[2*p+1], CB + 64 + oc);
    }
    int gs = (wid==0) ? 0 : 2*wid-1;
    int gc = (wid==0 || wid==4) ? 1 : 2;
    for (int g = gs; g < gs+gc; g++){
      ull ac[16];
      int ip[8];
      #pragma unroll
      for (int p = 0; p < 8; p++){ ac[2*p]=0; ac[2*p+1]=0; ip[p] = g*8+p; }
      tapN<8>(W1, xb, ip, oc, ac);
      #pragma unroll
      for (int p = 0; p < 8; p++)
        *(float4*)&g_cc[b][36+g*8+p][oc] = fin4(ac[2*p], ac[2*p+1], CB + 192 + oc);
    }
  } else {
    int ozg = wid - 5;
    ull ac[18];
    #pragma unroll
    for (int p = 0; p < 18; p++) ac[p] = 0;
    for (int kz=0;kz<2;kz++) for(int ky=0;ky<2;ky++) for(int kx=0;kx<2;kx++){
      int ip[9];
      #pragma unroll
      for (int p = 0; p < 9; p++){ int oy=p/3, ox=p%3; ip[p] = ((ozg+kz)*4 + oy+ky)*4 + ox+kx; }
      tapN<9>(W2 + ((kz*2+ky)*2+kx)*4096, xb, ip, oc, ac);
    }
    #pragma unroll
    for (int p = 0; p < 9; p++)
      *(float4*)&g_cc[b][9+ozg*9+p][oc] = fin4(ac[2*p], ac[2*p+1], CB + 128 + oc);
  }
}

// ---------------- fused attention v2: 256 threads, 2 CTAs/SM ----------------
// sum(mha_out) collapses o@V and out-proj:
// s0 = sum_hk (sum_s colsum_softmax[s]*v[s,hk]) * rowsumWo[hk] + SEQ*sum(bo)
// Probs never stored: warp shfl-butterfly reduces 8 rows -> s_part[16][SEQ].
template<int SEQ, int WHICH>
__global__ void __launch_bounds__(256) k_att(int layer, int nskip,
                      const float* __restrict__ qkv_w, const float* __restrict__ qkv_b,
                      const float* __restrict__ out_w, const float* __restrict__ out_b,
                      const float* __restrict__ ff_w,
                      const float* __restrict__ an_g, const float* __restrict__ an_b,
                      const float* __restrict__ sgp, const float* __restrict__ sbp){
  extern __shared__ float sm[];
  constexpr int QS = SEQ/4;
  float* s_q    = sm;                    // [8][SEQ][8]
  float* s_k    = s_q + 8*SEQ*8;
  float* s_v    = s_k + 8*SEQ*8;
  float* s_part = s_v + 8*SEQ*8;         // [16][SEQ]
  float* s_ws   = s_part + 16*SEQ;       // [SEQ]
  float* s_wv   = s_ws + SEQ;            // 64
  float* s_red  = s_wv + 64;             // 512 (partials [0..8), result [256])
  int b = blockIdx.x, tid = threadIdx.x;
  int lane = tid & 31, wrp = tid >> 5;
  const float* xsrc = (WHICH == 0) ? &g_cc[b][0][0] : &g_fbT[b][0][0][0];

  // Phase A: qkv for all heads; x streamed from global (warp-uniform rows)
  const float* QW = qkv_w + (size_t)(layer*2+WHICH)*12288;
  const float* QB = qkv_b + (layer*2+WHICH)*192;
  if (tid < 192){
    int ty = tid >> 6, c = tid & 63, h = c >> 3, kk = c & 7;
    ull wreg2[32];
    const float* wp = QW + ty*4096 + c;
    #pragma unroll
    for (int i = 0; i < 32; i++) wreg2[i] = pack2(wp[(2*i)*64], wp[(2*i+1)*64]);
    ull bias2 = pack2(QB[ty*64 + c], 0.f);
    float* dst = (ty == 0 ? s_q : ty == 1 ? s_k : s_v) + h*SEQ*8 + kk;
    for (int s = 0; s < SEQ; s++){
      const ulonglong2* xr = (const ulonglong2*)(xsrc + s*64);
      ull accA = bias2, accB = 0ull;
      #pragma unroll
      for (int i = 0; i < 16; i++){
        ulonglong2 xv = xr[i];
        fma2(accA, xv.x, wreg2[2*i]);
        fma2(accB, xv.y, wreg2[2*i+1]);
      }
      dst[s*8] = fsum2(accA) + fsum2(accB);
    }
  }
  __syncthreads();

  const float scale = 0.3535533905932738f;
  for (int h = 0; h < 8; h++){
    // scores + softmax in 2 row-batches of 64; colsum partials via warp butterfly
    #pragma unroll
    for (int rb = 0; rb < SEQ; rb += 64){
      int r = rb + (tid >> 2), qd = tid & 3;
      bool valid = (r < SEQ);
      int rc = valid ? r : 0;                       // clamp: keep warp converged
      const ulonglong2* qp = (const ulonglong2*)(s_q + (h*SEQ + rc)*8);
      ulonglong2 q01 = qp[0], q23 = qp[1];
      float rowv[QS];
      float mx = -1e30f;
      #pragma unroll
      for (int i = 0; i < QS; i++){
        int si = 4*i + qd;
        const ulonglong2* kp = (const ulonglong2*)(s_k + (h*SEQ + si)*8);
        ulonglong2 k01 = kp[0], k23 = kp[1];
        ull acc = 0ull;
        fma2(acc, q01.x, k01.x); fma2(acc, q01.y, k01.y);
        fma2(acc, q23.x, k23.x); fma2(acc, q23.y, k23.y);
        float a = fsum2(acc)*scale;
        rowv[i] = a; mx = fmaxf(mx, a);
      }
      mx = fmaxf(mx, __shfl_xor_sync(~0u, mx, 1));
      mx = fmaxf(mx, __shfl_xor_sync(~0u, mx, 2));
      float sum = 0.f;
      #pragma unroll
      for (int i = 0; i < QS; i++){ float e = __expf(rowv[i]-mx); rowv[i] = e; sum += e; }
      sum += __shfl_xor_sync(~0u, sum, 1);
      sum += __shfl_xor_sync(~0u, sum, 2);
      float inv = 1.f/sum;
      int slot = wrp + (rb >> 6)*8;                  // [0,16)
      #pragma unroll
      for (int i = 0; i < QS; i++){
        float pv = valid ? rowv[i]*inv : 0.f;
        pv += __shfl_xor_sync(~0u, pv, 4);           // sum over 8 rows in warp
        pv += __shfl_xor_sync(~0u, pv, 8);
        pv += __shfl_xor_sync(~0u, pv, 16);
        if (lane < 4) s_part[slot*SEQ + 4*i + lane] = pv;
      }
    }
    __syncthreads();
    if (tid < SEQ){
      float a = 0.f;
      #pragma unroll
      for (int w2 = 0; w2 < 16; w2++) a += s_part[w2*SEQ + tid];
      s_ws[tid] = a;
    }
    __syncthreads();
    if (tid < 64){
      int kk2 = tid >> 3, ch = tid & 7;
      float acc = 0.f;
      for (int s = ch; s < SEQ; s += 8) acc += s_ws[s] * s_v[(h*SEQ + s)*8 + kk2];
      acc += __shfl_xor_sync(~0u, acc, 1);
      acc += __shfl_xor_sync(~0u, acc, 2);
      acc += __shfl_xor_sync(~0u, acc, 4);
      if (ch == 0) s_wv[h*8 + kk2] = acc;
    }
    __syncthreads();
  }

  // s0 = sum_hk wv[hk]*rowsumWo[hk] + SEQ*sum(bo)
  const float* OW = out_w + (size_t)(layer*2+WHICH)*4096;
  const float* OB = out_b + (layer*2+WHICH)*64;
  float part;
  {
    int hk = tid >> 2, ch = tid & 3;                // hk in [0,64), ch in [0,4)
    float acc = 0.f;
    #pragma unroll
    for (int d = 0; d < 16; d++) acc += OW[hk*64 + ch*16 + d];
    acc += __shfl_xor_sync(~0u, acc, 1);
    acc += __shfl_xor_sync(~0u, acc, 2);
    part = (ch == 0) ? s_wv[hk]*acc : 0.f;
    if (tid < 64) part += (float)SEQ * OB[tid];
  }
  { float w = wred32(part); if (lane == 0) s_red[wrp] = w; }
  __syncthreads();
  if (tid < 32){
    float v = (tid < 8) ? s_red[tid] : 0.f;
    v = wred32(v);
    if (tid == 0) s_red[256] = v;
  }
  __syncthreads();
  float s0 = s_red[256];
  __syncthreads();

  // ff: s1 = sum relu(s0*W0)
  const float* W0 = ff_w + (size_t)((layer*2+WHICH)*2)*4096;
  const float* W1 = W0 + 4096;
  part = 0.f;
  for (int idx = tid; idx < 4096; idx += 256) part += fmaxf(s0*W0[idx], 0.f);
  { float w = wred32(part); if (lane == 0) s_red[wrp] = w; }
  __syncthreads();
  if (tid < 32){
    float v = (tid < 8) ? s_red[tid] : 0.f;
    v = wred32(v);
    if (tid == 0) s_red[256] = v;
  }
  __syncthreads();
  float s1 = s_red[256];

  // LN (+ skip chain for WHICH=1): all 256 threads
  {
    int p = tid >> 2, q = tid & 3;
    const float* G  = an_g + (layer*2+WHICH)*64;
    const float* Bb = an_b + (layer*2+WHICH)*64;
    const float* resid = WHICH ? &g_d0[b][0][0] : &g_last[b][0][0];
    float cur[16]; float sum = 0.f, sq = 0.f;
    #pragma unroll
    for (int c = 0; c < 16; c++){
      int d = q*16 + c;
      float v = s1*W1[p*64 + d] + resid[p*64 + d];
      cur[c] = v; sum += v; sq += v*v;
    }
    sum += __shfl_xor_sync(~0u, sum, 1); sum += __shfl_xor_sync(~0u, sum, 2);
    sq  += __shfl_xor_sync(~0u, sq , 1); sq  += __shfl_xor_sync(~0u, sq , 2);
    float mean = sum*(1.f/64.f);
    float var  = sq*(1.f/64.f) - mean*mean;
    float inv  = rsqrtf(var + EPSV);
    #pragma unroll
    for (int c = 0; c < 16; c++){
      int d = q*16 + c;
      cur[c] = (cur[c] - mean)*inv*G[d] + Bb[d];
    }
    if (WHICH == 0){
      #pragma unroll
      for (int c = 0; c < 16; c++){
        int d = q*16 + c;
        g_d0[b][p][d] = cur[c];
        g_d0T[b][d][p] = cur[c];
      }
    } else {
      #pragma unroll
      for (int c = 0; c < 16; c++){
        int d = q*16 + c;
        g_byp[layer][b][p][d] = cur[c];
      }
      for (int ss = 0; ss < nskip; ss++){
        int src = layer - (1 << ss) + 1;
        const float* Gs = sgp + (layer*4 + ss)*64;
        const float* Bs = sbp + (layer*4 + ss)*64;
        float sum2 = 0.f, sq2 = 0.f; float t[16];
        #pragma unroll
        for (int c = 0; c < 16; c++){
          int d = q*16 + c;
          float add = (src == layer) ? cur[c] : g_byp[src][b][p][d];
          float v = cur[c] + add;
          t[c] = v; sum2 += v; sq2 += v*v;
        }
        sum2 += __shfl_xor_sync(~0u, sum2, 1); sum2 += __shfl_xor_sync(~0u, sum2, 2);
        sq2  += __shfl_xor_sync(~0u, sq2 , 1); sq2  += __shfl_xor_sync(~0u, sq2 , 2);
        float m2 = sum2*(1.f/64.f);
        float v2 = sq2*(1.f/64.f) - m2*m2;
        float i2 = rsqrtf(v2 + EPSV);
        #pragma unroll
        for (int c = 0; c < 16; c++){
          int d = q*16 + c;
          cur[c] = (t[c] - m2)*i2*Gs[d] + Bs[d];
        }
      }
      #pragma unroll
      for (int c = 0; c < 16; c++){
        int d = q*16 + c;
        g_last[b][p][d] = cur[c];
      }
    }
  }
}

// ---------------- fused GRU: xg GEMM (smem) + recurrence ----------------
__global__ void __launch_bounds__(192) k_gru(int layer,
                      const float* __restrict__ gk, const float* __restrict__ gr,
                      const float* __restrict__ gb){
  extern __shared__ float sg[];
  float* s_dT = sg;            // 4096
  float* s_xg = sg + 4096;     // 64*192
  float* s_h  = s_xg + 12288;  // 64
  float* s_hg = s_h + 64;      // 192
  int blk = blockIdx.x, b = blk >> 1, dir = blk & 1;
  int j = threadIdx.x;
  for (int idx = j; idx < 4096; idx += 192) s_dT[idx] = (&g_d0T[b][0][0])[idx];
  const float* K = gk + (size_t)(layer*2+dir)*12288;
  const float* R = gr + (size_t)(layer*2+dir)*12288;
  ull bias2 = pack2(gb[((layer*2+dir)*2 + 0)*192 + j], 0.f);
  ull wr2[32];
  #pragma unroll
  for (int i = 0; i < 32; i++) wr2[i] = pack2(K[(2*i)*192 + j], K[(2*i+1)*192 + j]);
  if (j < 64) s_h[j] = g_mstate[b][layer][dir][j];
  __syncthreads();
  for (int t0 = 0; t0 < 64; t0 += 2){
    int tcA = dir ? (63 - t0) : t0;
    int tcB = dir ? (62 - t0) : (t0 + 1);
    const ulonglong2* xA = (const ulonglong2*)(s_dT + tcA*64);
    const ulonglong2* xB = (const ulonglong2*)(s_dT + tcB*64);
    ull aA = bias2, aB = 0ull, bA = bias2, bB = 0ull;
    #pragma unroll
    for (int i = 0; i < 16; i++){
      ulonglong2 va = xA[i];
      ulonglong2 vb = xB[i];
      fma2(aA, va.x, wr2[2*i]); fma2(aB, va.y, wr2[2*i+1]);
      fma2(bA, vb.x, wr2[2*i]); fma2(bB, vb.y, wr2[2*i+1]);
    }
    s_xg[t0*192 + j]     = fsum2(aA) + fsum2(aB);
    s_xg[(t0+1)*192 + j] = fsum2(bA) + fsum2(bB);
  }
  ull br2 = pack2(gb[((layer*2+dir)*2 + 1)*192 + j], 0.f);
  #pragma unroll
  for (int i = 0; i < 32; i++) wr2[i] = pack2(R[(2*i)*192 + j], R[(2*i+1)*192 + j]);
  __syncthreads();
  for (int t = 0; t < 64; t++){
    const ulonglong2* h4 = (const ulonglong2*)s_h;
    ull a0 = br2, a1 = 0ull, a2 = 0ull, a3 = 0ull;
    #pragma unroll
    for (int i = 0; i < 8; i++){
      ulonglong2 hv = h4[i];
      ulonglong2 hw = h4[i+8];
      fma2(a0, hv.x, wr2[2*i]);      fma2(a1, hv.y, wr2[2*i+1]);
      fma2(a2, hw.x, wr2[16+2*i]);   fma2(a3, hw.y, wr2[16+2*i+1]);
    }
    s_hg[j] = (fsum2(a0) + fsum2(a1)) + (fsum2(a2) + fsum2(a3));
    __syncthreads();
    if (j < 64){
      float xz = s_xg[t*192 + j], xr2 = s_xg[t*192 + 64 + j], xh = s_xg[t*192 + 128 + j];
      float z  = 1.f/(1.f + __expf(-(xz  + s_hg[j])));
      float rt = 1.f/(1.f + __expf(-(xr2 + s_hg[64 + j])));
      float c  = tanhf(xh + rt*s_hg[128 + j]);
      float hn = z*s_h[j] + (1.f - z)*c;
      s_h[j] = hn;
      g_fbT[b][dir][j][t] = hn;   // transposed write for k_att phase A
    }
    __syncthreads();
  }
  if (j < 64) g_states[b][layer][dir][j] = s_h[j];
}

__global__ void k_final(float* __restrict__ out){
  int b = blockIdx.x;
  float* o1 = out;
  float* o2 = out + (size_t)BN*5120;
  for (int idx = threadIdx.x; idx < 64*80; idx += blockDim.x){
    int p = idx/80, c = idx%80;
    float v;
    if (c < 64) v = g_last[b][p][c];
    else { int cc = c - 64; v = g_states[b][cc>>1][cc&1][p]; }
    o1[b*5120 + idx] = v;
  }
  for (int idx = threadIdx.x; idx < 1024; idx += blockDim.x){
    int cp = idx >> 6, f = idx & 63;
    o2[b*1024 + idx] = g_states[b][cp>>1][cp&1][f];
  }
}

extern "C" void kernel_launch(void* const* d_in, const int* in_sizes, int n_in,
                              void* d_out, int out_size){
  const float* x      = (const float*)d_in[0];
  const float* state  = (const float*)d_in[1];
  const float* conv_w4= (const float*)d_in[2];
  const float* conv_w3= (const float*)d_in[3];
  const float* conv_w2= (const float*)d_in[4];
  const float* conv_w1= (const float*)d_in[5];
  const float* conv_b = (const float*)d_in[6];
  const float* qkv_w  = (const float*)d_in[7];
  const float* qkv_b  = (const float*)d_in[8];
  const float* out_w  = (const float*)d_in[9];
  const float* out_b  = (const float*)d_in[10];
  const float* ff_w   = (const float*)d_in[11];
  const float* an_g   = (const float*)d_in[12];
  const float* an_b   = (const float*)d_in[13];
  const float* gru_k  = (const float*)d_in[14];
  const float* gru_r  = (const float*)d_in[15];
  const float* gru_b  = (const float*)d_in[16];
  const float* skip_g = (const float*)d_in[17];
  const float* skip_b = (const float*)d_in[18];

  int smem0 = (209*100 + 576) * 4;   // 85,904
  int smem1 = (209*128 + 576) * 4;   // 109,312
  int smemG = (4096 + 64*192 + 64 + 192) * 4;
  static int attr_done = 0;
  if (!attr_done){
    cudaFuncSetAttribute(k_att<100,0>, cudaFuncAttributeMaxDynamicSharedMemorySize, smem0);
    cudaFuncSetAttribute(k_att<128,1>, cudaFuncAttributeMaxDynamicSharedMemorySize, smem1);
    cudaFuncSetAttribute(k_gru, cudaFuncAttributeMaxDynamicSharedMemorySize, smemG);
    attr_done = 1;
  }

  k_init<<<BN, 256>>>(x, state);
  for (int i = 0; i < LL; i++){
    int ns = 0;
    for (int j = 1; (i+1) % j == 0; j *= 2) ns++;
    k_conv<<<BN/2, 256>>>(i, conv_w4, conv_w3, conv_w2, conv_w1, conv_b);
    k_att<100,0><<<BN, 256, smem0>>>(i, 0, qkv_w, qkv_b, out_w, out_b, ff_w, an_g, an_b, skip_g, skip_b);
    k_gru<<<BN*2, 192, smemG>>>(i, gru_k, gru_r, gru_b);
    k_att<128,1><<<BN, 256, smem1>>>(i, ns, qkv_w, qkv_b, out_w, out_b, ff_w, an_g, an_b, skip_g, skip_b);
  }
  k_final<<<BN, 256>>>((float*)d_out);
}

// round 12
// speedup vs baseline: 1.2751x; 1.2751x over previous
#include <cuda_runtime.h>
#include <math.h>

#define BN 256
#define LL 8
#define EPSV 1e-3f

typedef unsigned long long ull;

__device__ __forceinline__ ull pack2(float a, float b){
  ull r; asm("mov.b64 %0,{%1,%2};" : "=l"(r) : "f"(a), "f"(b)); return r;
}
__device__ __forceinline__ ull dup2(float a){
  ull r; asm("mov.b64 %0,{%1,%1};" : "=l"(r) : "f"(a)); return r;
}
__device__ __forceinline__ void fma2(ull &d, ull a, ull b){
  asm("fma.rn.f32x2 %0,%1,%2,%0;" : "+l"(d) : "l"(a), "l"(b));
}
__device__ __forceinline__ float fsum2(ull v){
  float lo, hi; asm("mov.b64 {%0,%1},%2;" : "=f"(lo), "=f"(hi) : "l"(v)); return lo + hi;
}
__device__ __forceinline__ float2 unpk(ull v){
  float lo, hi; asm("mov.b64 {%0,%1},%2;" : "=f"(lo), "=f"(hi) : "l"(v)); return make_float2(lo, hi);
}
__device__ __forceinline__ float wred32(float v){
  v += __shfl_xor_sync(~0u, v, 16); v += __shfl_xor_sync(~0u, v, 8);
  v += __shfl_xor_sync(~0u, v, 4);  v += __shfl_xor_sync(~0u, v, 2);
  v += __shfl_xor_sync(~0u, v, 1);  return v;
}

__device__ float g_last[BN][64][64];
__device__ float g_cc[BN][100][64];
__device__ float g_d0[BN][64][64];
__device__ float g_d0T[BN][64][64];
__device__ float g_fb[BN][2][64][64];
__device__ float g_mstate[BN][LL][2][64];
__device__ float g_states[BN][LL][2][64];
__device__ float g_byp[LL][BN][64][64];

__global__ void k_init(const float* __restrict__ x, const float* __restrict__ state){
  int b = blockIdx.x;
  for (int idx = threadIdx.x; idx < 64*80; idx += blockDim.x){
    int p = idx/80, c = idx%80;
    if (c < 64) g_last[b][p][c] = x[b*5120 + idx];
  }
  for (int idx = threadIdx.x; idx < 1024; idx += blockDim.x){
    int cp = idx >> 6, f = idx & 63;
    g_mstate[b][cp>>1][cp&1][f] = state[b*1024 + idx] + x[b*5120 + f*80 + 64 + cp];
  }
}

// ---------------- conv (f32x2 packed) ----------------
template<int NP>
__device__ __forceinline__ void tapN(const float* __restrict__ W, const float* __restrict__ xb,
                                     const int* ip, int oc, ull* a){
  #pragma unroll 2
  for (int c4 = 0; c4 < 16; c4++){
    float4 xv[NP];
    #pragma unroll
    for (int p = 0; p < NP; p++) xv[p] = *(const float4*)(xb + ip[p]*64 + c4*4);
    #pragma unroll
    for (int cc = 0; cc < 4; cc++){
      ulonglong2 w2 = *(const ulonglong2*)(W + (c4*4+cc)*64 + oc);
      #pragma unroll
      for (int p = 0; p < NP; p++){
        float x1 = (cc==0)?xv[p].x:(cc==1)?xv[p].y:(cc==2)?xv[p].z:xv[p].w;
        ull xx = dup2(x1);
        fma2(a[2*p], xx, w2.x);
        fma2(a[2*p+1], xx, w2.y);
      }
    }
  }
}

__device__ __forceinline__ float4 fin4(ull a0, ull a1, const float* bp){
  float2 p01 = unpk(a0), p23 = unpk(a1);
  return make_float4(p01.x + bp[0], p01.y + bp[1], p23.x + bp[2], p23.y + bp[3]);
}

__global__ void __launch_bounds__(256) k_conv(int layer,
                       const float* __restrict__ w4, const float* __restrict__ w3,
                       const float* __restrict__ w2, const float* __restrict__ w1,
                       const float* __restrict__ cb){
  __shared__ float xs[2][64][64];
  int b0 = blockIdx.x * 2;
  for (int idx = threadIdx.x; idx < 8192; idx += 256){
    int bb = idx >> 12, r = idx & 4095;
    (&xs[bb][0][0])[r] = (&g_last[b0+bb][0][0])[r];
  }
  __syncthreads();
  int lane = threadIdx.x & 31, wid = threadIdx.x >> 5;
  int bsel = lane >> 4, oc = (lane & 15)*4;
  const float* xb = &xs[bsel][0][0];
  int b = b0 + bsel;
  const float* W4 = w4 + (size_t)layer*262144;
  const float* W3 = w3 + (size_t)layer*110592;
  const float* W2 = w2 + (size_t)layer*32768;
  const float* W1 = w1 + (size_t)layer*4096;
  const float* CB = cb + layer*256;

  if (wid <= 4){
    if (wid == 0){
      ull a[2] = {0ull, 0ull};
      for (int t = 0; t < 64; t++){ int ip[1] = {t}; tapN<1>(W4 + t*4096, xb, ip, oc, a); }
      *(float4*)&g_cc[b][0][oc] = fin4(a[0], a[1], CB + oc);
    } else {
      int po = (wid-1)*2;
      int oz = po>>2, oy = (po>>1)&1;
      ull ac[4] = {0,0,0,0};
      for (int kz=0;kz<3;kz++) for(int ky=0;ky<3;ky++) for(int kx=0;kx<3;kx++){
        int base = ((oz+kz)*4 + oy+ky)*4 + kx;
        int ip[2] = {base, base+1};
        tapN<2>(W3 + ((kz*3+ky)*3+kx)*4096, xb, ip, oc, ac);
      }
      #pragma unroll
      for (int p = 0; p < 2; p++)
        *(float4*)&g_cc[b][1+po+p][oc] = fin4(ac[2*p], ac[2*p+1], CB + 64 + oc);
    }
    int gs = (wid==0) ? 0 : 2*wid-1;
    int gc = (wid==0 || wid==4) ? 1 : 2;
    for (int g = gs; g < gs+gc; g++){
      ull ac[16];
      int ip[8];
      #pragma unroll
      for (int p = 0; p < 8; p++){ ac[2*p]=0; ac[2*p+1]=0; ip[p] = g*8+p; }
      tapN<8>(W1, xb, ip, oc, ac);
      #pragma unroll
      for (int p = 0; p < 8; p++)
        *(float4*)&g_cc[b][36+g*8+p][oc] = fin4(ac[2*p], ac[2*p+1], CB + 192 + oc);
    }
  } else {
    int ozg = wid - 5;
    ull ac[18];
    #pragma unroll
    for (int p = 0; p < 18; p++) ac[p] = 0;
    for (int kz=0;kz<2;kz++) for(int ky=0;ky<2;ky++) for(int kx=0;kx<2;kx++){
      int ip[9];
      #pragma unroll
      for (int p = 0; p < 9; p++){ int oy=p/3, ox=p%3; ip[p] = ((ozg+kz)*4 + oy+ky)*4 + ox+kx; }
      tapN<9>(W2 + ((kz*2+ky)*2+kx)*4096, xb, ip, oc, ac);
    }
    #pragma unroll
    for (int p = 0; p < 9; p++)
      *(float4*)&g_cc[b][9+ozg*9+p][oc] = fin4(ac[2*p], ac[2*p+1], CB + 128 + oc);
  }
}

// ---------------- fused attention + ff + LN (+skip for WHICH=1), f32x2 ----------------
// sum(mha_out) collapses o@V and out-proj:
// s0 = sum_hk (sum_s colsum_softmax[s]*v[s,hk]) * rowsumWo[hk] + SEQ*sum(bo)
// Probs never stored: warp shfl-butterfly reduces 8 rows -> s_part[16][SEQ].
template<int SEQ, int WHICH>
__global__ void __launch_bounds__(512) k_att(int layer, int nskip,
                      const float* __restrict__ qkv_w, const float* __restrict__ qkv_b,
                      const float* __restrict__ out_w, const float* __restrict__ out_b,
                      const float* __restrict__ ff_w,
                      const float* __restrict__ an_g, const float* __restrict__ an_b,
                      const float* __restrict__ sgp, const float* __restrict__ sbp){
  extern __shared__ float sm[];
  constexpr int RP  = 68;
  constexpr int QS  = SEQ / 4;
  float* s_qkv = sm;                    // [3][SEQ][RP]
  float* s_un  = s_qkv + 3*SEQ*RP;      // x [SEQ][RP]
  float* s_part= s_un + SEQ*RP;         // [16][SEQ]
  float* s_ws8 = s_part + 16*SEQ;       // [8][SEQ]
  float* s_wv  = s_ws8 + 8*SEQ;         // 64
  float* s_red = s_wv + 64;             // 512
  int b = blockIdx.x, tid = threadIdx.x;
  int lane = tid & 31, wrp = tid >> 5;

  if (WHICH == 0){
    for (int idx = tid; idx < SEQ*64; idx += 512){
      int s = idx >> 6, d = idx & 63;
      s_un[s*RP + d] = g_cc[b][s][d];
    }
  } else {
    for (int idx = tid; idx < SEQ*64; idx += 512){
      int f = idx & 63, t = (idx >> 6) & 63, dr = idx >> 12;
      s_un[(dr*64 + f)*RP + t] = g_fb[b][dr][t][f];
    }
  }
  __syncthreads();

  // Phase A: qkv for ALL heads (384 threads, packed weights in regs)
  const float* QW = qkv_w + (size_t)(layer*2+WHICH)*12288;
  const float* QB = qkv_b + (layer*2+WHICH)*192;
  if (tid < 384){
    int j = tid % 192, sh = tid / 192;
    int ty = j / 64, c = j % 64;
    ull wreg2[32];
    const float* wp = QW + ty*4096 + c;
    #pragma unroll
    for (int i = 0; i < 32; i++) wreg2[i] = pack2(wp[(2*i)*64], wp[(2*i+1)*64]);
    ull bias2 = pack2(QB[ty*64 + c], 0.f);
    float* dst = s_qkv + ty*SEQ*RP;
    for (int s = sh*(SEQ/2); s < (sh+1)*(SEQ/2); s++){
      const ulonglong2* xr = (const ulonglong2*)(s_un + s*RP);
      ull accA = bias2, accB = 0ull;
      #pragma unroll
      for (int i = 0; i < 16; i++){
        ulonglong2 xv = xr[i];
        fma2(accA, xv.x, wreg2[2*i]);
        fma2(accB, xv.y, wreg2[2*i+1]);
      }
      dst[s*RP + c] = fsum2(accA) + fsum2(accB);
    }
  }
  __syncthreads();

  float* s_q = s_qkv;
  float* s_k = s_qkv + SEQ*RP;
  float* s_v = s_qkv + 2*SEQ*RP;
  const float scale = 0.3535533905932738f;

  for (int h = 0; h < 8; h++){
    // scores + softmax; colsum partials via warp butterfly (rows clamped, warps full)
    {
      int r4 = tid >> 2, qd = tid & 3;
      bool valid = (r4 < SEQ);
      int r = valid ? r4 : 0;
      const ulonglong2* qp = (const ulonglong2*)(s_q + r*RP + h*8);
      ulonglong2 q01 = qp[0], q23 = qp[1];
      float rowv[QS];
      float mx = -1e30f;
      #pragma unroll
      for (int i = 0; i < QS; i++){
        int si = 4*i + qd;
        const ulonglong2* kp = (const ulonglong2*)(s_k + si*RP + h*8);
        ulonglong2 k01 = kp[0], k23 = kp[1];
        ull acc = 0ull;
        fma2(acc, q01.x, k01.x); fma2(acc, q01.y, k01.y);
        fma2(acc, q23.x, k23.x); fma2(acc, q23.y, k23.y);
        float a = fsum2(acc) * scale;
        rowv[i] = a; mx = fmaxf(mx, a);
      }
      mx = fmaxf(mx, __shfl_xor_sync(~0u, mx, 1));
      mx = fmaxf(mx, __shfl_xor_sync(~0u, mx, 2));
      float sum = 0.f;
      #pragma unroll
      for (int i = 0; i < QS; i++){ float e = __expf(rowv[i]-mx); rowv[i] = e; sum += e; }
      sum += __shfl_xor_sync(~0u, sum, 1);
      sum += __shfl_xor_sync(~0u, sum, 2);
      float inv = 1.f/sum;
      #pragma unroll
      for (int i = 0; i < QS; i++){
        float pv = valid ? rowv[i]*inv : 0.f;
        pv += __shfl_xor_sync(~0u, pv, 4);     // sum over 8 rows in warp
        pv += __shfl_xor_sync(~0u, pv, 8);
        pv += __shfl_xor_sync(~0u, pv, 16);
        if (lane < 4) s_part[wrp*SEQ + 4*i + lane] = pv;
      }
    }
    __syncthreads();
    if (tid < SEQ){
      float a = 0.f;
      #pragma unroll
      for (int w2 = 0; w2 < 16; w2++) a += s_part[w2*SEQ + tid];
      s_ws8[h*SEQ + tid] = a;
    }
    __syncthreads();
  }

  // wv[hk] = sum_s ws8[h][s]*v[s][hk]
  {
    int hk = tid >> 3, ch = tid & 7;
    int h = hk >> 3;
    float acc = 0.f;
    for (int s = ch; s < SEQ; s += 8) acc += s_ws8[h*SEQ + s] * s_v[s*RP + hk];
    s_red[tid] = acc;
  }
  __syncthreads();
  if (tid < 64){
    float acc = 0.f;
    #pragma unroll
    for (int ch = 0; ch < 8; ch++) acc += s_red[tid*8 + ch];
    s_wv[tid] = acc;
  }
  __syncthreads();

  // s0 = sum_hk wv[hk]*rowsumWo[hk] + SEQ*sum(bo)
  const float* OW = out_w + (size_t)(layer*2+WHICH)*4096;
  const float* OB = out_b + (layer*2+WHICH)*64;
  float part;
  {
    int hk = tid >> 3, ch = tid & 7;
    float acc = 0.f;
    #pragma unroll
    for (int d = 0; d < 8; d++) acc += OW[hk*64 + ch*8 + d];
    acc += __shfl_xor_sync(~0u, acc, 4);
    acc += __shfl_xor_sync(~0u, acc, 2);
    acc += __shfl_xor_sync(~0u, acc, 1);
    part = (ch == 0) ? s_wv[hk]*acc : 0.f;
    if (tid < 64) part += (float)SEQ * OB[tid];
  }
  { float w = wred32(part); if (lane == 0) s_red[wrp] = w; }
  __syncthreads();
  if (tid < 32){
    float v = (tid < 16) ? s_red[tid] : 0.f;
    v = wred32(v);
    if (tid == 0) s_red[256] = v;
  }
  __syncthreads();
  float s0 = s_red[256];
  __syncthreads();

  // ff: s1 = sum relu(s0*W0)
  const float* W0 = ff_w + (size_t)((layer*2+WHICH)*2)*4096;
  const float* W1 = W0 + 4096;
  part = 0.f;
  for (int idx = tid; idx < 4096; idx += 512) part += fmaxf(s0*W0[idx], 0.f);
  { float w = wred32(part); if (lane == 0) s_red[wrp] = w; }
  __syncthreads();
  if (tid < 32){
    float v = (tid < 16) ? s_red[tid] : 0.f;
    v = wred32(v);
    if (tid == 0) s_red[256] = v;
  }
  __syncthreads();
  float s1 = s_red[256];

  if (tid < 256){
    int p = tid >> 2, q = tid & 3;
    const float* G  = an_g + (layer*2+WHICH)*64;
    const float* Bb = an_b + (layer*2+WHICH)*64;
    const float* resid = WHICH ? &g_d0[b][0][0] : &g_last[b][0][0];
    float cur[16]; float sum = 0.f, sq = 0.f;
    #pragma unroll
    for (int c = 0; c < 16; c++){
      int d = q*16 + c;
      float v = s1*W1[p*64 + d] + resid[p*64 + d];
      cur[c] = v; sum += v; sq += v*v;
    }
    sum += __shfl_xor_sync(~0u, sum, 1); sum += __shfl_xor_sync(~0u, sum, 2);
    sq  += __shfl_xor_sync(~0u, sq , 1); sq  += __shfl_xor_sync(~0u, sq , 2);
    float mean = sum*(1.f/64.f);
    float var  = sq*(1.f/64.f) - mean*mean;
    float inv  = rsqrtf(var + EPSV);
    #pragma unroll
    for (int c = 0; c < 16; c++){
      int d = q*16 + c;
      cur[c] = (cur[c] - mean)*inv*G[d] + Bb[d];
    }
    if (WHICH == 0){
      #pragma unroll
      for (int c = 0; c < 16; c++){
        int d = q*16 + c;
        g_d0[b][p][d] = cur[c];
        g_d0T[b][d][p] = cur[c];
      }
    } else {
      #pragma unroll
      for (int c = 0; c < 16; c++){
        int d = q*16 + c;
        g_byp[layer][b][p][d] = cur[c];
      }
      for (int ss = 0; ss < nskip; ss++){
        int src = layer - (1 << ss) + 1;
        const float* Gs = sgp + (layer*4 + ss)*64;
        const float* Bs = sbp + (layer*4 + ss)*64;
        float sum2 = 0.f, sq2 = 0.f; float t[16];
        #pragma unroll
        for (int c = 0; c < 16; c++){
          int d = q*16 + c;
          float add = (src == layer) ? cur[c] : g_byp[src][b][p][d];
          float v = cur[c] + add;
          t[c] = v; sum2 += v; sq2 += v*v;
        }
        sum2 += __shfl_xor_sync(~0u, sum2, 1); sum2 += __shfl_xor_sync(~0u, sum2, 2);
        sq2  += __shfl_xor_sync(~0u, sq2 , 1); sq2  += __shfl_xor_sync(~0u, sq2 , 2);
        float m2 = sum2*(1.f/64.f);
        float v2 = sq2*(1.f/64.f) - m2*m2;
        float i2 = rsqrtf(v2 + EPSV);
        #pragma unroll
        for (int c = 0; c < 16; c++){
          int d = q*16 + c;
          cur[c] = (t[c] - m2)*i2*Gs[d] + Bs[d];
        }
      }
      #pragma unroll
      for (int c = 0; c < 16; c++){
        int d = q*16 + c;
        g_last[b][p][d] = cur[c];
      }
    }
  }
}

// ---------------- fused GRU: xg GEMM (smem) + recurrence ----------------
__global__ void __launch_bounds__(192) k_gru(int layer,
                      const float* __restrict__ gk, const float* __restrict__ gr,
                      const float* __restrict__ gb){
  extern __shared__ float sg[];
  float* s_dT = sg;            // 4096
  float* s_xg = sg + 4096;     // 64*192
  float* s_h  = s_xg + 12288;  // 64
  float* s_hg = s_h + 64;      // 192
  int blk = blockIdx.x, b = blk >> 1, dir = blk & 1;
  int j = threadIdx.x;
  for (int idx = j; idx < 4096; idx += 192) s_dT[idx] = (&g_d0T[b][0][0])[idx];
  const float* K = gk + (size_t)(layer*2+dir)*12288;
  const float* R = gr + (size_t)(layer*2+dir)*12288;
  ull bias2 = pack2(gb[((layer*2+dir)*2 + 0)*192 + j], 0.f);
  ull wr2[32];
  #pragma unroll
  for (int i = 0; i < 32; i++) wr2[i] = pack2(K[(2*i)*192 + j], K[(2*i+1)*192 + j]);
  if (j < 64) s_h[j] = g_mstate[b][layer][dir][j];
  __syncthreads();
  for (int t0 = 0; t0 < 64; t0 += 2){
    int tcA = dir ? (63 - t0) : t0;
    int tcB = dir ? (62 - t0) : (t0 + 1);
    const ulonglong2* xA = (const ulonglong2*)(s_dT + tcA*64);
    const ulonglong2* xB = (const ulonglong2*)(s_dT + tcB*64);
    ull aA = bias2, aB = 0ull, bA = bias2, bB = 0ull;
    #pragma unroll
    for (int i = 0; i < 16; i++){
      ulonglong2 va = xA[i];
      ulonglong2 vb = xB[i];
      fma2(aA, va.x, wr2[2*i]); fma2(aB, va.y, wr2[2*i+1]);
      fma2(bA, vb.x, wr2[2*i]); fma2(bB, vb.y, wr2[2*i+1]);
    }
    s_xg[t0*192 + j]     = fsum2(aA) + fsum2(aB);
    s_xg[(t0+1)*192 + j] = fsum2(bA) + fsum2(bB);
  }
  ull br2 = pack2(gb[((layer*2+dir)*2 + 1)*192 + j], 0.f);
  #pragma unroll
  for (int i = 0; i < 32; i++) wr2[i] = pack2(R[(2*i)*192 + j], R[(2*i+1)*192 + j]);
  __syncthreads();
  for (int t = 0; t < 64; t++){
    const ulonglong2* h4 = (const ulonglong2*)s_h;
    ull a0 = br2, a1 = 0ull, a2 = 0ull, a3 = 0ull;
    #pragma unroll
    for (int i = 0; i < 8; i++){
      ulonglong2 hv = h4[i];
      ulonglong2 hw = h4[i+8];
      fma2(a0, hv.x, wr2[2*i]);      fma2(a1, hv.y, wr2[2*i+1]);
      fma2(a2, hw.x, wr2[16+2*i]);   fma2(a3, hw.y, wr2[16+2*i+1]);
    }
    s_hg[j] = (fsum2(a0) + fsum2(a1)) + (fsum2(a2) + fsum2(a3));
    __syncthreads();
    if (j < 64){
      float xz = s_xg[t*192 + j], xr2 = s_xg[t*192 + 64 + j], xh = s_xg[t*192 + 128 + j];
      float z  = 1.f/(1.f + __expf(-(xz  + s_hg[j])));
      float rt = 1.f/(1.f + __expf(-(xr2 + s_hg[64 + j])));
      float c  = tanhf(xh + rt*s_hg[128 + j]);
      float hn = z*s_h[j] + (1.f - z)*c;
      s_h[j] = hn;
      g_fb[b][dir][t][j] = hn;
    }
    __syncthreads();
  }
  if (j < 64) g_states[b][layer][dir][j] = s_h[j];
}

__global__ void k_final(float* __restrict__ out){
  int b = blockIdx.x;
  float* o1 = out;
  float* o2 = out + (size_t)BN*5120;
  for (int idx = threadIdx.x; idx < 64*80; idx += blockDim.x){
    int p = idx/80, c = idx%80;
    float v;
    if (c < 64) v = g_last[b][p][c];
    else { int cc = c - 64; v = g_states[b][cc>>1][cc&1][p]; }
    o1[b*5120 + idx] = v;
  }
  for (int idx = threadIdx.x; idx < 1024; idx += blockDim.x){
    int cp = idx >> 6, f = idx & 63;
    o2[b*1024 + idx] = g_states[b][cp>>1][cp&1][f];
  }
}

extern "C" void kernel_launch(void* const* d_in, const int* in_sizes, int n_in,
                              void* d_out, int out_size){
  const float* x      = (const float*)d_in[0];
  const float* state  = (const float*)d_in[1];
  const float* conv_w4= (const float*)d_in[2];
  const float* conv_w3= (const float*)d_in[3];
  const float* conv_w2= (const float*)d_in[4];
  const float* conv_w1= (const float*)d_in[5];
  const float* conv_b = (const float*)d_in[6];
  const float* qkv_w  = (const float*)d_in[7];
  const float* qkv_b  = (const float*)d_in[8];
  const float* out_w  = (const float*)d_in[9];
  const float* out_b  = (const float*)d_in[10];
  const float* ff_w   = (const float*)d_in[11];
  const float* an_g   = (const float*)d_in[12];
  const float* an_b   = (const float*)d_in[13];
  const float* gru_k  = (const float*)d_in[14];
  const float* gru_r  = (const float*)d_in[15];
  const float* gru_b  = (const float*)d_in[16];
  const float* skip_g = (const float*)d_in[17];
  const float* skip_b = (const float*)d_in[18];

  int smem0 = (4*100*68 + 16*100 + 8*100 + 64 + 512) * 4;   // 120,704
  int smem1 = (4*128*68 + 16*128 + 8*128 + 64 + 512) * 4;   // 153,856
  int smemG = (4096 + 64*192 + 64 + 192) * 4;
  static int attr_done = 0;
  if (!attr_done){
    cudaFuncSetAttribute(k_att<100,0>, cudaFuncAttributeMaxDynamicSharedMemorySize, smem0);
    cudaFuncSetAttribute(k_att<128,1>, cudaFuncAttributeMaxDynamicSharedMemorySize, smem1);
    cudaFuncSetAttribute(k_gru, cudaFuncAttributeMaxDynamicSharedMemorySize, smemG);
    attr_done = 1;
  }

  k_init<<<BN, 256>>>(x, state);
  for (int i = 0; i < LL; i++){
    int ns = 0;
    for (int j = 1; (i+1) % j == 0; j *= 2) ns++;
    k_conv<<<BN/2, 256>>>(i, conv_w4, conv_w3, conv_w2, conv_w1, conv_b);
    k_att<100,0><<<BN, 512, smem0>>>(i, 0, qkv_w, qkv_b, out_w, out_b, ff_w, an_g, an_b, skip_g, skip_b);
    k_gru<<<BN*2, 192, smemG>>>(i, gru_k, gru_r, gru_b);
    k_att<128,1><<<BN, 512, smem1>>>(i, ns, qkv_w, qkv_b, out_w, out_b, ff_w, an_g, an_b, skip_g, skip_b);
  }
  k_final<<<BN, 256>>>((float*)d_out);
}

// round 13
// speedup vs baseline: 1.3487x; 1.0577x over previous
#include <cuda_runtime.h>
#include <math.h>

#define BN 256
#define LL 8
#define EPSV 1e-3f

typedef unsigned long long ull;

__device__ __forceinline__ ull pack2(float a, float b){
  ull r; asm("mov.b64 %0,{%1,%2};" : "=l"(r) : "f"(a), "f"(b)); return r;
}
__device__ __forceinline__ ull dup2(float a){
  ull r; asm("mov.b64 %0,{%1,%1};" : "=l"(r) : "f"(a)); return r;
}
__device__ __forceinline__ void fma2(ull &d, ull a, ull b){
  asm("fma.rn.f32x2 %0,%1,%2,%0;" : "+l"(d) : "l"(a), "l"(b));
}
__device__ __forceinline__ float fsum2(ull v){
  float lo, hi; asm("mov.b64 {%0,%1},%2;" : "=f"(lo), "=f"(hi) : "l"(v)); return lo + hi;
}
__device__ __forceinline__ float2 unpk(ull v){
  float lo, hi; asm("mov.b64 {%0,%1},%2;" : "=f"(lo), "=f"(hi) : "l"(v)); return make_float2(lo, hi);
}
__device__ __forceinline__ float wred32(float v){
  v += __shfl_xor_sync(~0u, v, 16); v += __shfl_xor_sync(~0u, v, 8);
  v += __shfl_xor_sync(~0u, v, 4);  v += __shfl_xor_sync(~0u, v, 2);
  v += __shfl_xor_sync(~0u, v, 1);  return v;
}

__device__ float g_last[BN][64][64];
__device__ float g_cc[BN][100][64];
__device__ float g_d0[BN][64][64];
__device__ float g_d0T[BN][64][64];
__device__ float g_fbT[BN][2][64][64];   // [b][dir][f][t] rows contiguous in t
__device__ float g_mstate[BN][LL][2][64];
__device__ float g_states[BN][LL][2][64];
__device__ float g_byp[LL][BN][64][64];

__global__ void k_init(const float* __restrict__ x, const float* __restrict__ state){
  int b = blockIdx.x;
  for (int idx = threadIdx.x; idx < 64*80; idx += blockDim.x){
    int p = idx/80, c = idx%80;
    if (c < 64) g_last[b][p][c] = x[b*5120 + idx];
  }
  for (int idx = threadIdx.x; idx < 1024; idx += blockDim.x){
    int cp = idx >> 6, f = idx & 63;
    g_mstate[b][cp>>1][cp&1][f] = state[b*1024 + idx] + x[b*5120 + f*80 + 64 + cp];
  }
}

// ---------------- conv (f32x2 packed) ----------------
template<int NP>
__device__ __forceinline__ void tapN(const float* __restrict__ W, const float* __restrict__ xb,
                                     const int* ip, int oc, ull* a){
  #pragma unroll 2
  for (int c4 = 0; c4 < 16; c4++){
    float4 xv[NP];
    #pragma unroll
    for (int p = 0; p < NP; p++) xv[p] = *(const float4*)(xb + ip[p]*64 + c4*4);
    #pragma unroll
    for (int cc = 0; cc < 4; cc++){
      ulonglong2 w2 = *(const ulonglong2*)(W + (c4*4+cc)*64 + oc);
      #pragma unroll
      for (int p = 0; p < NP; p++){
        float x1 = (cc==0)?xv[p].x:(cc==1)?xv[p].y:(cc==2)?xv[p].z:xv[p].w;
        ull xx = dup2(x1);
        fma2(a[2*p], xx, w2.x);
        fma2(a[2*p+1], xx, w2.y);
      }
    }
  }
}

__device__ __forceinline__ float4 fin4(ull a0, ull a1, const float* bp){
  float2 p01 = unpk(a0), p23 = unpk(a1);
  return make_float4(p01.x + bp[0], p01.y + bp[1], p23.x + bp[2], p23.y + bp[3]);
}

__global__ void __launch_bounds__(256) k_conv(int layer,
                       const float* __restrict__ w4, const float* __restrict__ w3,
                       const float* __restrict__ w2, const float* __restrict__ w1,
                       const float* __restrict__ cb){
  __shared__ float xs[2][64][64];
  int b0 = blockIdx.x * 2;
  for (int idx = threadIdx.x; idx < 8192; idx += 256){
    int bb = idx >> 12, r = idx & 4095;
    (&xs[bb][0][0])[r] = (&g_last[b0+bb][0][0])[r];
  }
  __syncthreads();
  int lane = threadIdx.x & 31, wid = threadIdx.x >> 5;
  int bsel = lane >> 4, oc = (lane & 15)*4;
  const float* xb = &xs[bsel][0][0];
  int b = b0 + bsel;
  const float* W4 = w4 + (size_t)layer*262144;
  const float* W3 = w3 + (size_t)layer*110592;
  const float* W2 = w2 + (size_t)layer*32768;
  const float* W1 = w1 + (size_t)layer*4096;
  const float* CB = cb + layer*256;

  if (wid <= 4){
    if (wid == 0){
      ull a[2] = {0ull, 0ull};
      for (int t = 0; t < 64; t++){ int ip[1] = {t}; tapN<1>(W4 + t*4096, xb, ip, oc, a); }
      *(float4*)&g_cc[b][0][oc] = fin4(a[0], a[1], CB + oc);
    } else {
      int po = (wid-1)*2;
      int oz = po>>2, oy = (po>>1)&1;
      ull ac[4] = {0,0,0,0};
      for (int kz=0;kz<3;kz++) for(int ky=0;ky<3;ky++) for(int kx=0;kx<3;kx++){
        int base = ((oz+kz)*4 + oy+ky)*4 + kx;
        int ip[2] = {base, base+1};
        tapN<2>(W3 + ((kz*3+ky)*3+kx)*4096, xb, ip, oc, ac);
      }
      #pragma unroll
      for (int p = 0; p < 2; p++)
        *(float4*)&g_cc[b][1+po+p][oc] = fin4(ac[2*p], ac[2*p+1], CB + 64 + oc);
    }
    int gs = (wid==0) ? 0 : 2*wid-1;
    int gc = (wid==0 || wid==4) ? 1 : 2;
    for (int g = gs; g < gs+gc; g++){
      ull ac[16];
      int ip[8];
      #pragma unroll
      for (int p = 0; p < 8; p++){ ac[2*p]=0; ac[2*p+1]=0; ip[p] = g*8+p; }
      tapN<8>(W1, xb, ip, oc, ac);
      #pragma unroll
      for (int p = 0; p < 8; p++)
        *(float4*)&g_cc[b][36+g*8+p][oc] = fin4(ac[2*p], ac[2*p+1], CB + 192 + oc);
    }
  } else {
    int ozg = wid - 5;
    ull ac[18];
    #pragma unroll
    for (int p = 0; p < 18; p++) ac[p] = 0;
    for (int kz=0;kz<2;kz++) for(int ky=0;ky<2;ky++) for(int kx=0;kx<2;kx++){
      int ip[9];
      #pragma unroll
      for (int p = 0; p < 9; p++){ int oy=p/3, ox=p%3; ip[p] = ((ozg+kz)*4 + oy+ky)*4 + ox+kx; }
      tapN<9>(W2 + ((kz*2+ky)*2+kx)*4096, xb, ip, oc, ac);
    }
    #pragma unroll
    for (int p = 0; p < 9; p++)
      *(float4*)&g_cc[b][9+ozg*9+p][oc] = fin4(ac[2*p], ac[2*p+1], CB + 128 + oc);
  }
}

// ---------------- fused attention v3: 256 threads, 2 CTAs/SM ----------------
// sum(mha_out) collapses o@V and out-proj:
// s0 = sum_hk (sum_s colsum_softmax[s]*v[s,hk]) * rowsumWo[hk] + SEQ*sum(bo)
// qkv head-major [3][8][SEQ][8]; x chunk-staged (32 rows) in region unioned with
// s_part/s_ws8; probs never stored (warp butterfly -> s_part[16][SEQ]).
template<int SEQ, int WHICH>
__global__ void __launch_bounds__(256, 2) k_att(int layer, int nskip,
                      const float* __restrict__ qkv_w, const float* __restrict__ qkv_b,
                      const float* __restrict__ out_w, const float* __restrict__ out_b,
                      const float* __restrict__ ff_w,
                      const float* __restrict__ an_g, const float* __restrict__ an_b,
                      const float* __restrict__ sgp, const float* __restrict__ sbp){
  extern __shared__ float sm[];
  constexpr int QS = SEQ/4;
  float* s_qkv = sm;                    // [3][8][SEQ][8] = 192*SEQ
  float* s_un  = sm + 192*SEQ;          // union: xbuf[32][64] | {s_part[16][SEQ], s_ws8[8][SEQ]}
  float* s_part= s_un;
  float* s_ws8 = s_un + 16*SEQ;
  float* s_wv  = s_un + 24*SEQ;         // 64
  float* s_red = s_wv + 64;             // 288
  int b = blockIdx.x, tid = threadIdx.x;
  int lane = tid & 31, wrp = tid >> 5;
  const float* xsrc = (WHICH == 0) ? &g_cc[b][0][0] : &g_fbT[b][0][0][0];

  // Phase A: qkv for all heads, x staged 32 rows per chunk (coalesced)
  const float* QW = qkv_w + (size_t)(layer*2+WHICH)*12288;
  const float* QB = qkv_b + (layer*2+WHICH)*192;
  ull wreg2[32]; ull bias2 = 0ull; float* dst = s_qkv;
  if (tid < 192){
    int ty = tid / 64, c = tid % 64, h = c >> 3, kk = c & 7;
    const float* wp = QW + ty*4096 + c;
    #pragma unroll
    for (int i = 0; i < 32; i++) wreg2[i] = pack2(wp[(2*i)*64], wp[(2*i+1)*64]);
    bias2 = pack2(QB[ty*64 + c], 0.f);
    dst = s_qkv + ty*8*SEQ*8 + h*SEQ*8 + kk;
  }
  for (int ck = 0; ck < SEQ; ck += 32){
    for (int idx = tid; idx < 2048; idx += 256){
      int s = ck + (idx >> 6);
      if (s < SEQ) s_un[idx] = xsrc[s*64 + (idx & 63)];
    }
    __syncthreads();
    if (tid < 192){
      for (int s2 = 0; s2 < 32; s2++){
        if (ck + s2 >= SEQ) break;
        const ulonglong2* xr = (const ulonglong2*)(s_un + s2*64);
        ull accA = bias2, accB = 0ull;
        #pragma unroll
        for (int i = 0; i < 16; i++){
          ulonglong2 xv = xr[i];
          fma2(accA, xv.x, wreg2[2*i]);
          fma2(accB, xv.y, wreg2[2*i+1]);
        }
        dst[(ck + s2)*8] = fsum2(accA) + fsum2(accB);
      }
    }
    __syncthreads();
  }

  float* s_q = s_qkv;
  float* s_k = s_qkv + 8*SEQ*8;
  float* s_v = s_qkv + 16*SEQ*8;
  const float scale = 0.3535533905932738f;

  for (int h = 0; h < 8; h++){
    // scores + softmax, 2 row-batches of 64 rows x 4 threads; butterfly -> s_part
    {
      int r0 = tid >> 2, qd = tid & 3;
      for (int rb = 0; rb < SEQ; rb += 64){
        int r = rb + r0;
        bool valid = (r < SEQ);
        int rc = valid ? r : 0;
        const ulonglong2* qp = (const ulonglong2*)(s_q + (h*SEQ + rc)*8);
        ulonglong2 q01 = qp[0], q23 = qp[1];
        float rowv[QS];
        float mx = -1e30f;
        #pragma unroll
        for (int i = 0; i < QS; i++){
          int si = 4*i + qd;
          const ulonglong2* kp = (const ulonglong2*)(s_k + (h*SEQ + si)*8);
          ulonglong2 k01 = kp[0], k23 = kp[1];
          ull acc = 0ull;
          fma2(acc, q01.x, k01.x); fma2(acc, q01.y, k01.y);
          fma2(acc, q23.x, k23.x); fma2(acc, q23.y, k23.y);
          float a = fsum2(acc)*scale;
          rowv[i] = a; mx = fmaxf(mx, a);
        }
        mx = fmaxf(mx, __shfl_xor_sync(~0u, mx, 1));
        mx = fmaxf(mx, __shfl_xor_sync(~0u, mx, 2));
        float sum = 0.f;
        #pragma unroll
        for (int i = 0; i < QS; i++){ float e = __expf(rowv[i]-mx); rowv[i] = e; sum += e; }
        sum += __shfl_xor_sync(~0u, sum, 1);
        sum += __shfl_xor_sync(~0u, sum, 2);
        float inv = 1.f/sum;
        int slot = wrp + (rb >> 6)*8;             // [0,16)
        #pragma unroll
        for (int i = 0; i < QS; i++){
          float pv = valid ? rowv[i]*inv : 0.f;
          pv += __shfl_xor_sync(~0u, pv, 4);      // sum over warp's 8 rows
          pv += __shfl_xor_sync(~0u, pv, 8);
          pv += __shfl_xor_sync(~0u, pv, 16);
          if (lane < 4) s_part[slot*SEQ + 4*i + lane] = pv;
        }
      }
    }
    __syncthreads();
    if (tid < SEQ){
      float a = 0.f;
      #pragma unroll
      for (int w2 = 0; w2 < 16; w2++) a += s_part[w2*SEQ + tid];
      s_ws8[h*SEQ + tid] = a;
    }
    __syncthreads();
  }

  // wv[hk] = sum_s ws8[h][s]*v[s][hk]
  {
    int hk = tid >> 2, ch = tid & 3;
    int h2 = hk >> 3, kk2 = hk & 7;
    float acc = 0.f;
    for (int s = ch; s < SEQ; s += 4) acc += s_ws8[h2*SEQ + s] * s_v[(h2*SEQ + s)*8 + kk2];
    acc += __shfl_xor_sync(~0u, acc, 1);
    acc += __shfl_xor_sync(~0u, acc, 2);
    if (ch == 0) s_wv[hk] = acc;
  }
  __syncthreads();

  // s0 = sum_hk wv[hk]*rowsumWo[hk] + SEQ*sum(bo)
  const float* OW = out_w + (size_t)(layer*2+WHICH)*4096;
  const float* OB = out_b + (layer*2+WHICH)*64;
  float part;
  {
    int hk = tid >> 2, ch = tid & 3;
    float acc = 0.f;
    #pragma unroll
    for (int d = 0; d < 16; d++) acc += OW[hk*64 + ch*16 + d];
    acc += __shfl_xor_sync(~0u, acc, 1);
    acc += __shfl_xor_sync(~0u, acc, 2);
    part = (ch == 0) ? s_wv[hk]*acc : 0.f;
    if (tid < 64) part += (float)SEQ * OB[tid];
  }
  { float w = wred32(part); if (lane == 0) s_red[wrp] = w; }
  __syncthreads();
  if (tid < 32){
    float v = (tid < 8) ? s_red[tid] : 0.f;
    v = wred32(v);
    if (tid == 0) s_red[64] = v;
  }
  __syncthreads();
  float s0 = s_red[64];
  __syncthreads();

  // ff: s1 = sum relu(s0*W0)
  const float* W0 = ff_w + (size_t)((layer*2+WHICH)*2)*4096;
  const float* W1 = W0 + 4096;
  part = 0.f;
  for (int idx = tid; idx < 4096; idx += 256) part += fmaxf(s0*W0[idx], 0.f);
  { float w = wred32(part); if (lane == 0) s_red[wrp] = w; }
  __syncthreads();
  if (tid < 32){
    float v = (tid < 8) ? s_red[tid] : 0.f;
    v = wred32(v);
    if (tid == 0) s_red[64] = v;
  }
  __syncthreads();
  float s1 = s_red[64];

  // LN (+ skip chain for WHICH=1)
  {
    int p = tid >> 2, q = tid & 3;
    const float* G  = an_g + (layer*2+WHICH)*64;
    const float* Bb = an_b + (layer*2+WHICH)*64;
    const float* resid = WHICH ? &g_d0[b][0][0] : &g_last[b][0][0];
    float cur[16]; float sum = 0.f, sq = 0.f;
    #pragma unroll
    for (int c = 0; c < 16; c++){
      int d = q*16 + c;
      float v = s1*W1[p*64 + d] + resid[p*64 + d];
      cur[c] = v; sum += v; sq += v*v;
    }
    sum += __shfl_xor_sync(~0u, sum, 1); sum += __shfl_xor_sync(~0u, sum, 2);
    sq  += __shfl_xor_sync(~0u, sq , 1); sq  += __shfl_xor_sync(~0u, sq , 2);
    float mean = sum*(1.f/64.f);
    float var  = sq*(1.f/64.f) - mean*mean;
    float inv  = rsqrtf(var + EPSV);
    #pragma unroll
    for (int c = 0; c < 16; c++){
      int d = q*16 + c;
      cur[c] = (cur[c] - mean)*inv*G[d] + Bb[d];
    }
    if (WHICH == 0){
      #pragma unroll
      for (int c = 0; c < 16; c++){
        int d = q*16 + c;
        g_d0[b][p][d] = cur[c];
        g_d0T[b][d][p] = cur[c];
      }
    } else {
      #pragma unroll
      for (int c = 0; c < 16; c++){
        int d = q*16 + c;
        g_byp[layer][b][p][d] = cur[c];
      }
      for (int ss = 0; ss < nskip; ss++){
        int src = layer - (1 << ss) + 1;
        const float* Gs = sgp + (layer*4 + ss)*64;
        const float* Bs = sbp + (layer*4 + ss)*64;
        float sum2 = 0.f, sq2 = 0.f; float t[16];
        #pragma unroll
        for (int c = 0; c < 16; c++){
          int d = q*16 + c;
          float add = (src == layer) ? cur[c] : g_byp[src][b][p][d];
          float v = cur[c] + add;
          t[c] = v; sum2 += v; sq2 += v*v;
        }
        sum2 += __shfl_xor_sync(~0u, sum2, 1); sum2 += __shfl_xor_sync(~0u, sum2, 2);
        sq2  += __shfl_xor_sync(~0u, sq2 , 1); sq2  += __shfl_xor_sync(~0u, sq2 , 2);
        float m2 = sum2*(1.f/64.f);
        float v2 = sq2*(1.f/64.f) - m2*m2;
        float i2 = rsqrtf(v2 + EPSV);
        #pragma unroll
        for (int c = 0; c < 16; c++){
          int d = q*16 + c;
          cur[c] = (t[c] - m2)*i2*Gs[d] + Bs[d];
        }
      }
      #pragma unroll
      for (int c = 0; c < 16; c++){
        int d = q*16 + c;
        g_last[b][p][d] = cur[c];
      }
    }
  }
}

// ---------------- fused GRU: xg GEMM (smem) + recurrence; hn staged -> g_fbT ----------------
__global__ void __launch_bounds__(192) k_gru(int layer,
                      const float* __restrict__ gk, const float* __restrict__ gr,
                      const float* __restrict__ gb){
  extern __shared__ float sg[];
  float* s_dT  = sg;             // [4096] (region is 4224; also reused as s_hnT)
  float* s_hnT = sg;             // [64][65] stride-65, used after xg phase
  float* s_xg  = sg + 4224;      // 64*192
  float* s_h   = s_xg + 12288;   // 64
  float* s_hg  = s_h + 64;       // 192
  int blk = blockIdx.x, b = blk >> 1, dir = blk & 1;
  int j = threadIdx.x;
  for (int idx = j; idx < 4096; idx += 192) s_dT[idx] = (&g_d0T[b][0][0])[idx];
  const float* K = gk + (size_t)(layer*2+dir)*12288;
  const float* R = gr + (size_t)(layer*2+dir)*12288;
  ull bias2 = pack2(gb[((layer*2+dir)*2 + 0)*192 + j], 0.f);
  ull wr2[32];
  #pragma unroll
  for (int i = 0; i < 32; i++) wr2[i] = pack2(K[(2*i)*192 + j], K[(2*i+1)*192 + j]);
  if (j < 64) s_h[j] = g_mstate[b][layer][dir][j];
  __syncthreads();
  for (int t0 = 0; t0 < 64; t0 += 2){
    int tcA = dir ? (63 - t0) : t0;
    int tcB = dir ? (62 - t0) : (t0 + 1);
    const ulonglong2* xA = (const ulonglong2*)(s_dT + tcA*64);
    const ulonglong2* xB = (const ulonglong2*)(s_dT + tcB*64);
    ull aA = bias2, aB = 0ull, bA = bias2, bB = 0ull;
    #pragma unroll
    for (int i = 0; i < 16; i++){
      ulonglong2 va = xA[i];
      ulonglong2 vb = xB[i];
      fma2(aA, va.x, wr2[2*i]); fma2(aB, va.y, wr2[2*i+1]);
      fma2(bA, vb.x, wr2[2*i]); fma2(bB, vb.y, wr2[2*i+1]);
    }
    s_xg[t0*192 + j]     = fsum2(aA) + fsum2(aB);
    s_xg[(t0+1)*192 + j] = fsum2(bA) + fsum2(bB);
  }
  ull br2 = pack2(gb[((layer*2+dir)*2 + 1)*192 + j], 0.f);
  #pragma unroll
  for (int i = 0; i < 32; i++) wr2[i] = pack2(R[(2*i)*192 + j], R[(2*i+1)*192 + j]);
  __syncthreads();                 // s_dT dead from here; region becomes s_hnT
  for (int t = 0; t < 64; t++){
    const ulonglong2* h4 = (const ulonglong2*)s_h;
    ull a0 = br2, a1 = 0ull, a2 = 0ull, a3 = 0ull;
    #pragma unroll
    for (int i = 0; i < 8; i++){
      ulonglong2 hv = h4[i];
      ulonglong2 hw = h4[i+8];
      fma2(a0, hv.x, wr2[2*i]);      fma2(a1, hv.y, wr2[2*i+1]);
      fma2(a2, hw.x, wr2[16+2*i]);   fma2(a3, hw.y, wr2[16+2*i+1]);
    }
    s_hg[j] = (fsum2(a0) + fsum2(a1)) + (fsum2(a2) + fsum2(a3));
    __syncthreads();
    if (j < 64){
      float xz = s_xg[t*192 + j], xr2 = s_xg[t*192 + 64 + j], xh = s_xg[t*192 + 128 + j];
      float z  = 1.f/(1.f + __expf(-(xz  + s_hg[j])));
      float rt = 1.f/(1.f + __expf(-(xr2 + s_hg[64 + j])));
      float c  = tanhf(xh + rt*s_hg[128 + j]);
      float hn = z*s_h[j] + (1.f - z)*c;
      s_h[j] = hn;
      s_hnT[j*65 + t] = hn;          // conflict-free staging
    }
    __syncthreads();
  }
  // coalesced copy to transposed global
  for (int idx = j; idx < 4096; idx += 192){
    int f = idx >> 6, t2 = idx & 63;
    g_fbT[b][dir][f][t2] = s_hnT[f*65 + t2];
  }
  if (j < 64) g_states[b][layer][dir][j] = s_h[j];
}

__global__ void k_final(float* __restrict__ out){
  int b = blockIdx.x;
  float* o1 = out;
  float* o2 = out + (size_t)BN*5120;
  for (int idx = threadIdx.x; idx < 64*80; idx += blockDim.x){
    int p = idx/80, c = idx%80;
    float v;
    if (c < 64) v = g_last[b][p][c];
    else { int cc = c - 64; v = g_states[b][cc>>1][cc&1][p]; }
    o1[b*5120 + idx] = v;
  }
  for (int idx = threadIdx.x; idx < 1024; idx += blockDim.x){
    int cp = idx >> 6, f = idx & 63;
    o2[b*1024 + idx] = g_states[b][cp>>1][cp&1][f];
  }
}

extern "C" void kernel_launch(void* const* d_in, const int* in_sizes, int n_in,
                              void* d_out, int out_size){
  const float* x      = (const float*)d_in[0];
  const float* state  = (const float*)d_in[1];
  const float* conv_w4= (const float*)d_in[2];
  const float* conv_w3= (const float*)d_in[3];
  const float* conv_w2= (const float*)d_in[4];
  const float* conv_w1= (const float*)d_in[5];
  const float* conv_b = (const float*)d_in[6];
  const float* qkv_w  = (const float*)d_in[7];
  const float* qkv_b  = (const float*)d_in[8];
  const float* out_w  = (const float*)d_in[9];
  const float* out_b  = (const float*)d_in[10];
  const float* ff_w   = (const float*)d_in[11];
  const float* an_g   = (const float*)d_in[12];
  const float* an_b   = (const float*)d_in[13];
  const float* gru_k  = (const float*)d_in[14];
  const float* gru_r  = (const float*)d_in[15];
  const float* gru_b  = (const float*)d_in[16];
  const float* skip_g = (const float*)d_in[17];
  const float* skip_b = (const float*)d_in[18];

  int smem0 = (216*100 + 352) * 4;   // 87,808
  int smem1 = (216*128 + 352) * 4;   // 112,000
  int smemG = (4224 + 12288 + 64 + 192) * 4;  // 67,072
  static int attr_done = 0;
  if (!attr_done){
    cudaFuncSetAttribute(k_att<100,0>, cudaFuncAttributeMaxDynamicSharedMemorySize, smem0);
    cudaFuncSetAttribute(k_att<128,1>, cudaFuncAttributeMaxDynamicSharedMemorySize, smem1);
    cudaFuncSetAttribute(k_gru, cudaFuncAttributeMaxDynamicSharedMemorySize, smemG);
    attr_done = 1;
  }

  k_init<<<BN, 256>>>(x, state);
  for (int i = 0; i < LL; i++){
    int ns = 0;
    for (int j = 1; (i+1) % j == 0; j *= 2) ns++;
    k_conv<<<BN/2, 256>>>(i, conv_w4, conv_w3, conv_w2, conv_w1, conv_b);
    k_att<100,0><<<BN, 256, smem0>>>(i, 0, qkv_w, qkv_b, out_w, out_b, ff_w, an_g, an_b, skip_g, skip_b);
    k_gru<<<BN*2, 192, smemG>>>(i, gru_k, gru_r, gru_b);
    k_att<128,1><<<BN, 256, smem1>>>(i, ns, qkv_w, qkv_b, out_w, out_b, ff_w, an_g, an_b, skip_g, skip_b);
  }
  k_final<<<BN, 256>>>((float*)d_out);
}

// round 14
// speedup vs baseline: 1.5663x; 1.1614x over previous
#include <cuda_runtime.h>
#include <math.h>

#define BN 256
#define LL 8
#define EPSV 1e-3f

typedef unsigned long long ull;

__device__ __forceinline__ ull pack2(float a, float b){
  ull r; asm("mov.b64 %0,{%1,%2};" : "=l"(r) : "f"(a), "f"(b)); return r;
}
__device__ __forceinline__ ull dup2(float a){
  ull r; asm("mov.b64 %0,{%1,%1};" : "=l"(r) : "f"(a)); return r;
}
__device__ __forceinline__ void fma2(ull &d, ull a, ull b){
  asm("fma.rn.f32x2 %0,%1,%2,%0;" : "+l"(d) : "l"(a), "l"(b));
}
__device__ __forceinline__ float fsum2(ull v){
  float lo, hi; asm("mov.b64 {%0,%1},%2;" : "=f"(lo), "=f"(hi) : "l"(v)); return lo + hi;
}
__device__ __forceinline__ float2 unpk(ull v){
  float lo, hi; asm("mov.b64 {%0,%1},%2;" : "=f"(lo), "=f"(hi) : "l"(v)); return make_float2(lo, hi);
}
__device__ __forceinline__ float wred32(float v){
  v += __shfl_xor_sync(~0u, v, 16); v += __shfl_xor_sync(~0u, v, 8);
  v += __shfl_xor_sync(~0u, v, 4);  v += __shfl_xor_sync(~0u, v, 2);
  v += __shfl_xor_sync(~0u, v, 1);  return v;
}

__device__ float g_last[BN][64][64];
__device__ float g_cc[BN][100][64];
__device__ float g_d0[BN][64][64];
__device__ float g_d0T[BN][64][64];
__device__ float g_fbT[BN][2][64][64];
__device__ float g_mstate[BN][LL][2][64];
__device__ float g_states[BN][LL][2][64];
__device__ float g_byp[LL][BN][64][64];

__global__ void k_init(const float* __restrict__ x, const float* __restrict__ state){
  int b = blockIdx.x;
  for (int idx = threadIdx.x; idx < 64*80; idx += blockDim.x){
    int p = idx/80, c = idx%80;
    if (c < 64) g_last[b][p][c] = x[b*5120 + idx];
  }
  for (int idx = threadIdx.x; idx < 1024; idx += blockDim.x){
    int cp = idx >> 6, f = idx & 63;
    g_mstate[b][cp>>1][cp&1][f] = state[b*1024 + idx] + x[b*5120 + f*80 + 64 + cp];
  }
}

// ---------------- conv: 1 batch/CTA, 16 balanced half-warp slots ----------------
template<int NP>
__device__ __forceinline__ void tapN(const float* __restrict__ W, const float* __restrict__ xb,
                                     const int* ip, int oc, ull* a){
  #pragma unroll 2
  for (int c4 = 0; c4 < 16; c4++){
    float4 xv[NP];
    #pragma unroll
    for (int p = 0; p < NP; p++) xv[p] = *(const float4*)(xb + ip[p]*64 + c4*4);
    #pragma unroll
    for (int cc = 0; cc < 4; cc++){
      ulonglong2 w2 = *(const ulonglong2*)(W + (c4*4+cc)*64 + oc);
      #pragma unroll
      for (int p = 0; p < NP; p++){
        float x1 = (cc==0)?xv[p].x:(cc==1)?xv[p].y:(cc==2)?xv[p].z:xv[p].w;
        ull xx = dup2(x1);
        fma2(a[2*p], xx, w2.x);
        fma2(a[2*p+1], xx, w2.y);
      }
    }
  }
}

__device__ __forceinline__ float4 fin4(ull a0, ull a1, const float* bp){
  float2 p01 = unpk(a0), p23 = unpk(a1);
  return make_float4(p01.x + bp[0], p01.y + bp[1], p23.x + bp[2], p23.y + bp[3]);
}

__global__ void __launch_bounds__(256) k_conv(int layer,
                       const float* __restrict__ w4, const float* __restrict__ w3,
                       const float* __restrict__ w2, const float* __restrict__ w1,
                       const float* __restrict__ cb){
  __shared__ float xs[64][64];
  __shared__ float s_c4[2][64];
  int b = blockIdx.x;
  for (int idx = threadIdx.x; idx < 4096; idx += 256)
    xs[0][idx] = (&g_last[b][0][0])[idx];
  __syncthreads();
  int lane = threadIdx.x & 31, wid = threadIdx.x >> 5;
  int psel = lane >> 4, oc = (lane & 15)*4;
  const float* xb = &xs[0][0];
  const float* W4 = w4 + (size_t)layer*262144;
  const float* W3 = w3 + (size_t)layer*110592;
  const float* W2 = w2 + (size_t)layer*32768;
  const float* W1 = w1 + (size_t)layer*4096;
  const float* CB = cb + layer*256;

  if (wid == 0){
    // c4 split taps: half psel does taps psel*32..+32 -> partial to smem
    ull a[2] = {0ull, 0ull};
    for (int t = 0; t < 32; t++){
      int tap = psel*32 + t;
      int ip[1] = {tap};
      tapN<1>(W4 + tap*4096, xb, ip, oc, a);
    }
    float2 p01 = unpk(a[0]), p23 = unpk(a[1]);
    *(float4*)&s_c4[psel][oc] = make_float4(p01.x, p01.y, p23.x, p23.y);
    // c1 group g = psel
    ull ac[16]; int ip[8];
    #pragma unroll
    for (int p = 0; p < 8; p++){ ac[2*p]=0; ac[2*p+1]=0; ip[p] = psel*8 + p; }
    tapN<8>(W1, xb, ip, oc, ac);
    #pragma unroll
    for (int p = 0; p < 8; p++)
      *(float4*)&g_cc[b][36+psel*8+p][oc] = fin4(ac[2*p], ac[2*p+1], CB + 192 + oc);
  } else if (wid <= 3){
    // c3 one pos per half
    int pos = (wid-1)*2 + psel;
    int oz = pos>>2, oy = (pos>>1)&1, ox = pos&1;
    ull a[2] = {0ull, 0ull};
    for (int kz=0;kz<3;kz++) for(int ky=0;ky<3;ky++) for(int kx=0;kx<3;kx++){
      int ip[1] = {((oz+kz)*4 + oy+ky)*4 + ox+kx};
      tapN<1>(W3 + ((kz*3+ky)*3+kx)*4096, xb, ip, oc, a);
    }
    *(float4*)&g_cc[b][1+pos][oc] = fin4(a[0], a[1], CB + 64 + oc);
    // c1 group g = wid*2 + psel (2..7)
    int g = wid*2 + psel;
    ull ac[16]; int ip[8];
    #pragma unroll
    for (int p = 0; p < 8; p++){ ac[2*p]=0; ac[2*p+1]=0; ip[p] = g*8 + p; }
    tapN<8>(W1, xb, ip, oc, ac);
    #pragma unroll
    for (int p = 0; p < 8; p++)
      *(float4*)&g_cc[b][36+g*8+p][oc] = fin4(ac[2*p], ac[2*p+1], CB + 192 + oc);
  } else if (wid == 4){
    // c3 pos 6/7
    int pos = 6 + psel;
    int oz = pos>>2, oy = (pos>>1)&1, ox = pos&1;
    ull a[2] = {0ull, 0ull};
    for (int kz=0;kz<3;kz++) for(int ky=0;ky<3;ky++) for(int kx=0;kx<3;kx++){
      int ip[1] = {((oz+kz)*4 + oy+ky)*4 + ox+kx};
      tapN<1>(W3 + ((kz*3+ky)*3+kx)*4096, xb, ip, oc, a);
    }
    *(float4*)&g_cc[b][1+pos][oc] = fin4(a[0], a[1], CB + 64 + oc);
  } else if (wid <= 6){
    // c2 5 pos per half: base 0,5,10,15
    int pbase = (wid-5)*10 + psel*5;
    ull ac[10];
    #pragma unroll
    for (int p = 0; p < 10; p++) ac[p] = 0;
    int pp[5];
    #pragma unroll
    for (int p = 0; p < 5; p++) pp[p] = pbase + p;
    for (int kz=0;kz<2;kz++) for(int ky=0;ky<2;ky++) for(int kx=0;kx<2;kx++){
      int ip[5];
      #pragma unroll
      for (int p = 0; p < 5; p++){
        int pos = pp[p];
        int oz = pos/9, oy = (pos/3)%3, ox = pos%3;
        ip[p] = ((oz+kz)*4 + oy+ky)*4 + ox+kx;
      }
      tapN<5>(W2 + ((kz*2+ky)*2+kx)*4096, xb, ip, oc, ac);
    }
    #pragma unroll
    for (int p = 0; p < 5; p++)
      *(float4*)&g_cc[b][9+pbase+p][oc] = fin4(ac[2*p], ac[2*p+1], CB + 128 + oc);
  } else {
    // c2 tail: psel0 {20,21,22,22}, psel1 {23,24,25,26}
    int p0 = 20 + psel*3;
    int pp[4] = {p0, p0+1, p0+2, p0+3 - (psel?0:1)};
    ull ac[8];
    #pragma unroll
    for (int p = 0; p < 8; p++) ac[p] = 0;
    for (int kz=0;kz<2;kz++) for(int ky=0;ky<2;ky++) for(int kx=0;kx<2;kx++){
      int ip[4];
      #pragma unroll
      for (int p = 0; p < 4; p++){
        int pos = pp[p];
        int oz = pos/9, oy = (pos/3)%3, ox = pos%3;
        ip[p] = ((oz+kz)*4 + oy+ky)*4 + ox+kx;
      }
      tapN<4>(W2 + ((kz*2+ky)*2+kx)*4096, xb, ip, oc, ac);
    }
    #pragma unroll
    for (int p = 0; p < 4; p++)
      *(float4*)&g_cc[b][9+pp[p]][oc] = fin4(ac[2*p], ac[2*p+1], CB + 128 + oc);
  }
  __syncthreads();
  if (threadIdx.x < 64)
    g_cc[b][0][threadIdx.x] = s_c4[0][threadIdx.x] + s_c4[1][threadIdx.x] + CB[threadIdx.x];
}

// ---------------- fused attention v3: 256 threads, 2 CTAs/SM ----------------
// sum(mha_out) collapses o@V and out-proj:
// s0 = sum_hk (sum_s colsum_softmax[s]*v[s,hk]) * rowsumWo[hk] + SEQ*sum(bo)
template<int SEQ, int WHICH>
__global__ void __launch_bounds__(256, 2) k_att(int layer, int nskip,
                      const float* __restrict__ qkv_w, const float* __restrict__ qkv_b,
                      const float* __restrict__ out_w, const float* __restrict__ out_b,
                      const float* __restrict__ ff_w,
                      const float* __restrict__ an_g, const float* __restrict__ an_b,
                      const float* __restrict__ sgp, const float* __restrict__ sbp){
  extern __shared__ float sm[];
  constexpr int QS = SEQ/4;
  float* s_qkv = sm;                    // [3][8][SEQ][8]
  float* s_un  = sm + 192*SEQ;          // union: xbuf[32][64] | {s_part[16][SEQ], s_ws8[8][SEQ]}
  float* s_part= s_un;
  float* s_ws8 = s_un + 16*SEQ;
  float* s_wv  = s_un + 24*SEQ;         // 64
  float* s_red = s_wv + 64;             // 288
  int b = blockIdx.x, tid = threadIdx.x;
  int lane = tid & 31, wrp = tid >> 5;
  const float* xsrc = (WHICH == 0) ? &g_cc[b][0][0] : &g_fbT[b][0][0][0];

  const float* QW = qkv_w + (size_t)(layer*2+WHICH)*12288;
  const float* QB = qkv_b + (layer*2+WHICH)*192;
  ull wreg2[32]; ull bias2 = 0ull; float* dst = s_qkv;
  if (tid < 192){
    int ty = tid / 64, c = tid % 64, h = c >> 3, kk = c & 7;
    const float* wp = QW + ty*4096 + c;
    #pragma unroll
    for (int i = 0; i < 32; i++) wreg2[i] = pack2(wp[(2*i)*64], wp[(2*i+1)*64]);
    bias2 = pack2(QB[ty*64 + c], 0.f);
    dst = s_qkv + ty*8*SEQ*8 + h*SEQ*8 + kk;
  }
  for (int ck = 0; ck < SEQ; ck += 32){
    for (int idx = tid; idx < 2048; idx += 256){
      int s = ck + (idx >> 6);
      if (s < SEQ) s_un[idx] = xsrc[s*64 + (idx & 63)];
    }
    __syncthreads();
    if (tid < 192){
      for (int s2 = 0; s2 < 32; s2++){
        if (ck + s2 >= SEQ) break;
        const ulonglong2* xr = (const ulonglong2*)(s_un + s2*64);
        ull accA = bias2, accB = 0ull;
        #pragma unroll
        for (int i = 0; i < 16; i++){
          ulonglong2 xv = xr[i];
          fma2(accA, xv.x, wreg2[2*i]);
          fma2(accB, xv.y, wreg2[2*i+1]);
        }
        dst[(ck + s2)*8] = fsum2(accA) + fsum2(accB);
      }
    }
    __syncthreads();
  }

  float* s_q = s_qkv;
  float* s_k = s_qkv + 8*SEQ*8;
  float* s_v = s_qkv + 16*SEQ*8;
  const float scale = 0.3535533905932738f;

  for (int h = 0; h < 8; h++){
    {
      int r0 = tid >> 2, qd = tid & 3;
      for (int rb = 0; rb < SEQ; rb += 64){
        int r = rb + r0;
        bool valid = (r < SEQ);
        int rc = valid ? r : 0;
        const ulonglong2* qp = (const ulonglong2*)(s_q + (h*SEQ + rc)*8);
        ulonglong2 q01 = qp[0], q23 = qp[1];
        float rowv[QS];
        float mx = -1e30f;
        #pragma unroll
        for (int i = 0; i < QS; i++){
          int si = 4*i + qd;
          const ulonglong2* kp = (const ulonglong2*)(s_k + (h*SEQ + si)*8);
          ulonglong2 k01 = kp[0], k23 = kp[1];
          ull acc = 0ull;
          fma2(acc, q01.x, k01.x); fma2(acc, q01.y, k01.y);
          fma2(acc, q23.x, k23.x); fma2(acc, q23.y, k23.y);
          float a = fsum2(acc)*scale;
          rowv[i] = a; mx = fmaxf(mx, a);
        }
        mx = fmaxf(mx, __shfl_xor_sync(~0u, mx, 1));
        mx = fmaxf(mx, __shfl_xor_sync(~0u, mx, 2));
        float sum = 0.f;
        #pragma unroll
        for (int i = 0; i < QS; i++){ float e = __expf(rowv[i]-mx); rowv[i] = e; sum += e; }
        sum += __shfl_xor_sync(~0u, sum, 1);
        sum += __shfl_xor_sync(~0u, sum, 2);
        float inv = 1.f/sum;
        int slot = wrp + (rb >> 6)*8;
        #pragma unroll
        for (int i = 0; i < QS; i++){
          float pv = valid ? rowv[i]*inv : 0.f;
          pv += __shfl_xor_sync(~0u, pv, 4);
          pv += __shfl_xor_sync(~0u, pv, 8);
          pv += __shfl_xor_sync(~0u, pv, 16);
          if (lane < 4) s_part[slot*SEQ + 4*i + lane] = pv;
        }
      }
    }
    __syncthreads();
    if (tid < SEQ){
      float a = 0.f;
      #pragma unroll
      for (int w2 = 0; w2 < 16; w2++) a += s_part[w2*SEQ + tid];
      s_ws8[h*SEQ + tid] = a;
    }
    __syncthreads();
  }

  {
    int hk = tid >> 2, ch = tid & 3;
    int h2 = hk >> 3, kk2 = hk & 7;
    float acc = 0.f;
    for (int s = ch; s < SEQ; s += 4) acc += s_ws8[h2*SEQ + s] * s_v[(h2*SEQ + s)*8 + kk2];
    acc += __shfl_xor_sync(~0u, acc, 1);
    acc += __shfl_xor_sync(~0u, acc, 2);
    if (ch == 0) s_wv[hk] = acc;
  }
  __syncthreads();

  const float* OW = out_w + (size_t)(layer*2+WHICH)*4096;
  const float* OB = out_b + (layer*2+WHICH)*64;
  float part;
  {
    int hk = tid >> 2, ch = tid & 3;
    float acc = 0.f;
    #pragma unroll
    for (int d = 0; d < 16; d++) acc += OW[hk*64 + ch*16 + d];
    acc += __shfl_xor_sync(~0u, acc, 1);
    acc += __shfl_xor_sync(~0u, acc, 2);
    part = (ch == 0) ? s_wv[hk]*acc : 0.f;
    if (tid < 64) part += (float)SEQ * OB[tid];
  }
  { float w = wred32(part); if (lane == 0) s_red[wrp] = w; }
  __syncthreads();
  if (tid < 32){
    float v = (tid < 8) ? s_red[tid] : 0.f;
    v = wred32(v);
    if (tid == 0) s_red[64] = v;
  }
  __syncthreads();
  float s0 = s_red[64];
  __syncthreads();

  const float* W0 = ff_w + (size_t)((layer*2+WHICH)*2)*4096;
  const float* W1 = W0 + 4096;
  part = 0.f;
  for (int idx = tid; idx < 4096; idx += 256) part += fmaxf(s0*W0[idx], 0.f);
  { float w = wred32(part); if (lane == 0) s_red[wrp] = w; }
  __syncthreads();
  if (tid < 32){
    float v = (tid < 8) ? s_red[tid] : 0.f;
    v = wred32(v);
    if (tid == 0) s_red[64] = v;
  }
  __syncthreads();
  float s1 = s_red[64];

  {
    int p = tid >> 2, q = tid & 3;
    const float* G  = an_g + (layer*2+WHICH)*64;
    const float* Bb = an_b + (layer*2+WHICH)*64;
    const float* resid = WHICH ? &g_d0[b][0][0] : &g_last[b][0][0];
    float cur[16]; float sum = 0.f, sq = 0.f;
    #pragma unroll
    for (int c = 0; c < 16; c++){
      int d = q*16 + c;
      float v = s1*W1[p*64 + d] + resid[p*64 + d];
      cur[c] = v; sum += v; sq += v*v;
    }
    sum += __shfl_xor_sync(~0u, sum, 1); sum += __shfl_xor_sync(~0u, sum, 2);
    sq  += __shfl_xor_sync(~0u, sq , 1); sq  += __shfl_xor_sync(~0u, sq , 2);
    float mean = sum*(1.f/64.f);
    float var  = sq*(1.f/64.f) - mean*mean;
    float inv  = rsqrtf(var + EPSV);
    #pragma unroll
    for (int c = 0; c < 16; c++){
      int d = q*16 + c;
      cur[c] = (cur[c] - mean)*inv*G[d] + Bb[d];
    }
    if (WHICH == 0){
      #pragma unroll
      for (int c = 0; c < 16; c++){
        int d = q*16 + c;
        g_d0[b][p][d] = cur[c];
        g_d0T[b][d][p] = cur[c];
      }
    } else {
      #pragma unroll
      for (int c = 0; c < 16; c++){
        int d = q*16 + c;
        g_byp[layer][b][p][d] = cur[c];
      }
      for (int ss = 0; ss < nskip; ss++){
        int src = layer - (1 << ss) + 1;
        const float* Gs = sgp + (layer*4 + ss)*64;
        const float* Bs = sbp + (layer*4 + ss)*64;
        float sum2 = 0.f, sq2 = 0.f; float t[16];
        #pragma unroll
        for (int c = 0; c < 16; c++){
          int d = q*16 + c;
          float add = (src == layer) ? cur[c] : g_byp[src][b][p][d];
          float v = cur[c] + add;
          t[c] = v; sum2 += v; sq2 += v*v;
        }
        sum2 += __shfl_xor_sync(~0u, sum2, 1); sum2 += __shfl_xor_sync(~0u, sum2, 2);
        sq2  += __shfl_xor_sync(~0u, sq2 , 1); sq2  += __shfl_xor_sync(~0u, sq2 , 2);
        float m2 = sum2*(1.f/64.f);
        float v2 = sq2*(1.f/64.f) - m2*m2;
        float i2 = rsqrtf(v2 + EPSV);
        #pragma unroll
        for (int c = 0; c < 16; c++){
          int d = q*16 + c;
          cur[c] = (t[c] - m2)*i2*Gs[d] + Bs[d];
        }
      }
      #pragma unroll
      for (int c = 0; c < 16; c++){
        int d = q*16 + c;
        g_last[b][p][d] = cur[c];
      }
    }
  }
}

// ---------------- fused GRU (R13-verified) ----------------
__global__ void __launch_bounds__(192) k_gru(int layer,
                      const float* __restrict__ gk, const float* __restrict__ gr,
                      const float* __restrict__ gb){
  extern __shared__ float sg[];
  float* s_dT  = sg;
  float* s_hnT = sg;
  float* s_xg  = sg + 4224;
  float* s_h   = s_xg + 12288;
  float* s_hg  = s_h + 64;
  int blk = blockIdx.x, b = blk >> 1, dir = blk & 1;
  int j = threadIdx.x;
  for (int idx = j; idx < 4096; idx += 192) s_dT[idx] = (&g_d0T[b][0][0])[idx];
  const float* K = gk + (size_t)(layer*2+dir)*12288;
  const float* R = gr + (size_t)(layer*2+dir)*12288;
  ull bias2 = pack2(gb[((layer*2+dir)*2 + 0)*192 + j], 0.f);
  ull wr2[32];
  #pragma unroll
  for (int i = 0; i < 32; i++) wr2[i] = pack2(K[(2*i)*192 + j], K[(2*i+1)*192 + j]);
  if (j < 64) s_h[j] = g_mstate[b][layer][dir][j];
  __syncthreads();
  for (int t0 = 0; t0 < 64; t0 += 2){
    int tcA = dir ? (63 - t0) : t0;
    int tcB = dir ? (62 - t0) : (t0 + 1);
    const ulonglong2* xA = (const ulonglong2*)(s_dT + tcA*64);
    const ulonglong2* xB = (const ulonglong2*)(s_dT + tcB*64);
    ull aA = bias2, aB = 0ull, bA = bias2, bB = 0ull;
    #pragma unroll
    for (int i = 0; i < 16; i++){
      ulonglong2 va = xA[i];
      ulonglong2 vb = xB[i];
      fma2(aA, va.x, wr2[2*i]); fma2(aB, va.y, wr2[2*i+1]);
      fma2(bA, vb.x, wr2[2*i]); fma2(bB, vb.y, wr2[2*i+1]);
    }
    s_xg[t0*192 + j]     = fsum2(aA) + fsum2(aB);
    s_xg[(t0+1)*192 + j] = fsum2(bA) + fsum2(bB);
  }
  ull br2 = pack2(gb[((layer*2+dir)*2 + 1)*192 + j], 0.f);
  #pragma unroll
  for (int i = 0; i < 32; i++) wr2[i] = pack2(R[(2*i)*192 + j], R[(2*i+1)*192 + j]);
  __syncthreads();
  for (int t = 0; t < 64; t++){
    const ulonglong2* h4 = (const ulonglong2*)s_h;
    ull a0 = br2, a1 = 0ull, a2 = 0ull, a3 = 0ull;
    #pragma unroll
    for (int i = 0; i < 8; i++){
      ulonglong2 hv = h4[i];
      ulonglong2 hw = h4[i+8];
      fma2(a0, hv.x, wr2[2*i]);      fma2(a1, hv.y, wr2[2*i+1]);
      fma2(a2, hw.x, wr2[16+2*i]);   fma2(a3, hw.y, wr2[16+2*i+1]);
    }
    s_hg[j] = (fsum2(a0) + fsum2(a1)) + (fsum2(a2) + fsum2(a3));
    __syncthreads();
    if (j < 64){
      float xz = s_xg[t*192 + j], xr2 = s_xg[t*192 + 64 + j], xh = s_xg[t*192 + 128 + j];
      float z  = 1.f/(1.f + __expf(-(xz  + s_hg[j])));
      float rt = 1.f/(1.f + __expf(-(xr2 + s_hg[64 + j])));
      float c  = tanhf(xh + rt*s_hg[128 + j]);
      float hn = z*s_h[j] + (1.f - z)*c;
      s_h[j] = hn;
      s_hnT[j*65 + t] = hn;
    }
    __syncthreads();
  }
  for (int idx = j; idx < 4096; idx += 192){
    int f = idx >> 6, t2 = idx & 63;
    g_fbT[b][dir][f][t2] = s_hnT[f*65 + t2];
  }
  if (j < 64) g_states[b][layer][dir][j] = s_h[j];
}

__global__ void k_final(float* __restrict__ out){
  int b = blockIdx.x;
  float* o1 = out;
  float* o2 = out + (size_t)BN*5120;
  for (int idx = threadIdx.x; idx < 64*80; idx += blockDim.x){
    int p = idx/80, c = idx%80;
    float v;
    if (c < 64) v = g_last[b][p][c];
    else { int cc = c - 64; v = g_states[b][cc>>1][cc&1][p]; }
    o1[b*5120 + idx] = v;
  }
  for (int idx = threadIdx.x; idx < 1024; idx += blockDim.x){
    int cp = idx >> 6, f = idx & 63;
    o2[b*1024 + idx] = g_states[b][cp>>1][cp&1][f];
  }
}

extern "C" void kernel_launch(void* const* d_in, const int* in_sizes, int n_in,
                              void* d_out, int out_size){
  const float* x      = (const float*)d_in[0];
  const float* state  = (const float*)d_in[1];
  const float* conv_w4= (const float*)d_in[2];
  const float* conv_w3= (const float*)d_in[3];
  const float* conv_w2= (const float*)d_in[4];
  const float* conv_w1= (const float*)d_in[5];
  const float* conv_b = (const float*)d_in[6];
  const float* qkv_w  = (const float*)d_in[7];
  const float* qkv_b  = (const float*)d_in[8];
  const float* out_w  = (const float*)d_in[9];
  const float* out_b  = (const float*)d_in[10];
  const float* ff_w   = (const float*)d_in[11];
  const float* an_g   = (const float*)d_in[12];
  const float* an_b   = (const float*)d_in[13];
  const float* gru_k  = (const float*)d_in[14];
  const float* gru_r  = (const float*)d_in[15];
  const float* gru_b  = (const float*)d_in[16];
  const float* skip_g = (const float*)d_in[17];
  const float* skip_b = (const float*)d_in[18];

  int smem0 = (216*100 + 352) * 4;
  int smem1 = (216*128 + 352) * 4;
  int smemG = (4224 + 12288 + 64 + 192) * 4;
  static int attr_done = 0;
  if (!attr_done){
    cudaFuncSetAttribute(k_att<100,0>, cudaFuncAttributeMaxDynamicSharedMemorySize, smem0);
    cudaFuncSetAttribute(k_att<128,1>, cudaFuncAttributeMaxDynamicSharedMemorySize, smem1);
    cudaFuncSetAttribute(k_gru, cudaFuncAttributeMaxDynamicSharedMemorySize, smemG);
    attr_done = 1;
  }

  k_init<<<BN, 256>>>(x, state);
  for (int i = 0; i < LL; i++){
    int ns = 0;
    for (int j = 1; (i+1) % j == 0; j *= 2) ns++;
    k_conv<<<BN, 256>>>(i, conv_w4, conv_w3, conv_w2, conv_w1, conv_b);
    k_att<100,0><<<BN, 256, smem0>>>(i, 0, qkv_w, qkv_b, out_w, out_b, ff_w, an_g, an_b, skip_g, skip_b);
    k_gru<<<BN*2, 192, smemG>>>(i, gru_k, gru_r, gru_b);
    k_att<128,1><<<BN, 256, smem1>>>(i, ns, qkv_w, qkv_b, out_w, out_b, ff_w, an_g, an_b, skip_g, skip_b);
  }
  k_final<<<BN, 256>>>((float*)d_out);
}

// round 15
// speedup vs baseline: 1.5742x; 1.0050x over previous
#include <cuda_runtime.h>
#include <math.h>

#define BN 256
#define LL 8
#define EPSV 1e-3f

typedef unsigned long long ull;

__device__ __forceinline__ ull pack2(float a, float b){
  ull r; asm("mov.b64 %0,{%1,%2};" : "=l"(r) : "f"(a), "f"(b)); return r;
}
__device__ __forceinline__ ull dup2(float a){
  ull r; asm("mov.b64 %0,{%1,%1};" : "=l"(r) : "f"(a)); return r;
}
__device__ __forceinline__ void fma2(ull &d, ull a, ull b){
  asm("fma.rn.f32x2 %0,%1,%2,%0;" : "+l"(d) : "l"(a), "l"(b));
}
__device__ __forceinline__ float fsum2(ull v){
  float lo, hi; asm("mov.b64 {%0,%1},%2;" : "=f"(lo), "=f"(hi) : "l"(v)); return lo + hi;
}
__device__ __forceinline__ float2 unpk(ull v){
  float lo, hi; asm("mov.b64 {%0,%1},%2;" : "=f"(lo), "=f"(hi) : "l"(v)); return make_float2(lo, hi);
}
__device__ __forceinline__ float wred32(float v){
  v += __shfl_xor_sync(~0u, v, 16); v += __shfl_xor_sync(~0u, v, 8);
  v += __shfl_xor_sync(~0u, v, 4);  v += __shfl_xor_sync(~0u, v, 2);
  v += __shfl_xor_sync(~0u, v, 1);  return v;
}

__device__ float g_last[BN][64][64];
__device__ float g_cc[BN][100][64];
__device__ float g_d0[BN][64][64];
__device__ float g_d0T[BN][64][64];
__device__ float g_fbT[BN][2][64][64];
__device__ float g_mstate[BN][LL][2][64];
__device__ float g_states[BN][LL][2][64];
__device__ float g_byp[LL][BN][64][64];

__global__ void k_init(const float* __restrict__ x, const float* __restrict__ state){
  int b = blockIdx.x;
  for (int idx = threadIdx.x; idx < 64*80; idx += blockDim.x){
    int p = idx/80, c = idx%80;
    if (c < 64) g_last[b][p][c] = x[b*5120 + idx];
  }
  for (int idx = threadIdx.x; idx < 1024; idx += blockDim.x){
    int cp = idx >> 6, f = idx & 63;
    g_mstate[b][cp>>1][cp&1][f] = state[b*1024 + idx] + x[b*5120 + f*80 + 64 + cp];
  }
}

// ---------------- conv: 1 batch/CTA, 16 balanced half-warp slots (R14-verified) ----------------
template<int NP>
__device__ __forceinline__ void tapN(const float* __restrict__ W, const float* __restrict__ xb,
                                     const int* ip, int oc, ull* a){
  #pragma unroll 2
  for (int c4 = 0; c4 < 16; c4++){
    float4 xv[NP];
    #pragma unroll
    for (int p = 0; p < NP; p++) xv[p] = *(const float4*)(xb + ip[p]*64 + c4*4);
    #pragma unroll
    for (int cc = 0; cc < 4; cc++){
      ulonglong2 w2 = *(const ulonglong2*)(W + (c4*4+cc)*64 + oc);
      #pragma unroll
      for (int p = 0; p < NP; p++){
        float x1 = (cc==0)?xv[p].x:(cc==1)?xv[p].y:(cc==2)?xv[p].z:xv[p].w;
        ull xx = dup2(x1);
        fma2(a[2*p], xx, w2.x);
        fma2(a[2*p+1], xx, w2.y);
      }
    }
  }
}

__device__ __forceinline__ float4 fin4(ull a0, ull a1, const float* bp){
  float2 p01 = unpk(a0), p23 = unpk(a1);
  return make_float4(p01.x + bp[0], p01.y + bp[1], p23.x + bp[2], p23.y + bp[3]);
}

__global__ void __launch_bounds__(256) k_conv(int layer,
                       const float* __restrict__ w4, const float* __restrict__ w3,
                       const float* __restrict__ w2, const float* __restrict__ w1,
                       const float* __restrict__ cb){
  __shared__ float xs[64][64];
  __shared__ float s_c4[2][64];
  int b = blockIdx.x;
  for (int idx = threadIdx.x; idx < 4096; idx += 256)
    xs[0][idx] = (&g_last[b][0][0])[idx];
  __syncthreads();
  int lane = threadIdx.x & 31, wid = threadIdx.x >> 5;
  int psel = lane >> 4, oc = (lane & 15)*4;
  const float* xb = &xs[0][0];
  const float* W4 = w4 + (size_t)layer*262144;
  const float* W3 = w3 + (size_t)layer*110592;
  const float* W2 = w2 + (size_t)layer*32768;
  const float* W1 = w1 + (size_t)layer*4096;
  const float* CB = cb + layer*256;

  if (wid == 0){
    ull a[2] = {0ull, 0ull};
    for (int t = 0; t < 32; t++){
      int tap = psel*32 + t;
      int ip[1] = {tap};
      tapN<1>(W4 + tap*4096, xb, ip, oc, a);
    }
    float2 p01 = unpk(a[0]), p23 = unpk(a[1]);
    *(float4*)&s_c4[psel][oc] = make_float4(p01.x, p01.y, p23.x, p23.y);
    ull ac[16]; int ip[8];
    #pragma unroll
    for (int p = 0; p < 8; p++){ ac[2*p]=0; ac[2*p+1]=0; ip[p] = psel*8 + p; }
    tapN<8>(W1, xb, ip, oc, ac);
    #pragma unroll
    for (int p = 0; p < 8; p++)
      *(float4*)&g_cc[b][36+psel*8+p][oc] = fin4(ac[2*p], ac[2*p+1], CB + 192 + oc);
  } else if (wid <= 3){
    int pos = (wid-1)*2 + psel;
    int oz = pos>>2, oy = (pos>>1)&1, ox = pos&1;
    ull a[2] = {0ull, 0ull};
    for (int kz=0;kz<3;kz++) for(int ky=0;ky<3;ky++) for(int kx=0;kx<3;kx++){
      int ip[1] = {((oz+kz)*4 + oy+ky)*4 + ox+kx};
      tapN<1>(W3 + ((kz*3+ky)*3+kx)*4096, xb, ip, oc, a);
    }
    *(float4*)&g_cc[b][1+pos][oc] = fin4(a[0], a[1], CB + 64 + oc);
    int g = wid*2 + psel;
    ull ac[16]; int ip[8];
    #pragma unroll
    for (int p = 0; p < 8; p++){ ac[2*p]=0; ac[2*p+1]=0; ip[p] = g*8 + p; }
    tapN<8>(W1, xb, ip, oc, ac);
    #pragma unroll
    for (int p = 0; p < 8; p++)
      *(float4*)&g_cc[b][36+g*8+p][oc] = fin4(ac[2*p], ac[2*p+1], CB + 192 + oc);
  } else if (wid == 4){
    int pos = 6 + psel;
    int oz = pos>>2, oy = (pos>>1)&1, ox = pos&1;
    ull a[2] = {0ull, 0ull};
    for (int kz=0;kz<3;kz++) for(int ky=0;ky<3;ky++) for(int kx=0;kx<3;kx++){
      int ip[1] = {((oz+kz)*4 + oy+ky)*4 + ox+kx};
      tapN<1>(W3 + ((kz*3+ky)*3+kx)*4096, xb, ip, oc, a);
    }
    *(float4*)&g_cc[b][1+pos][oc] = fin4(a[0], a[1], CB + 64 + oc);
  } else if (wid <= 6){
    int pbase = (wid-5)*10 + psel*5;
    ull ac[10];
    #pragma unroll
    for (int p = 0; p < 10; p++) ac[p] = 0;
    int pp[5];
    #pragma unroll
    for (int p = 0; p < 5; p++) pp[p] = pbase + p;
    for (int kz=0;kz<2;kz++) for(int ky=0;ky<2;ky++) for(int kx=0;kx<2;kx++){
      int ip[5];
      #pragma unroll
      for (int p = 0; p < 5; p++){
        int pos = pp[p];
        int oz = pos/9, oy = (pos/3)%3, ox = pos%3;
        ip[p] = ((oz+kz)*4 + oy+ky)*4 + ox+kx;
      }
      tapN<5>(W2 + ((kz*2+ky)*2+kx)*4096, xb, ip, oc, ac);
    }
    #pragma unroll
    for (int p = 0; p < 5; p++)
      *(float4*)&g_cc[b][9+pbase+p][oc] = fin4(ac[2*p], ac[2*p+1], CB + 128 + oc);
  } else {
    int p0 = 20 + psel*3;
    int pp[4] = {p0, p0+1, p0+2, p0+3 - (psel?0:1)};
    ull ac[8];
    #pragma unroll
    for (int p = 0; p < 8; p++) ac[p] = 0;
    for (int kz=0;kz<2;kz++) for(int ky=0;ky<2;ky++) for(int kx=0;kx<2;kx++){
      int ip[4];
      #pragma unroll
      for (int p = 0; p < 4; p++){
        int pos = pp[p];
        int oz = pos/9, oy = (pos/3)%3, ox = pos%3;
        ip[p] = ((oz+kz)*4 + oy+ky)*4 + ox+kx;
      }
      tapN<4>(W2 + ((kz*2+ky)*2+kx)*4096, xb, ip, oc, ac);
    }
    #pragma unroll
    for (int p = 0; p < 4; p++)
      *(float4*)&g_cc[b][9+pp[p]][oc] = fin4(ac[2*p], ac[2*p+1], CB + 128 + oc);
  }
  __syncthreads();
  if (threadIdx.x < 64)
    g_cc[b][0][threadIdx.x] = s_c4[0][threadIdx.x] + s_c4[1][threadIdx.x] + CB[threadIdx.x];
}

// ---------------- fused attention v4: phase A with 2-row ILP ----------------
// sum(mha_out) collapses o@V and out-proj:
// s0 = sum_hk (sum_s colsum_softmax[s]*v[s,hk]) * rowsumWo[hk] + SEQ*sum(bo)
template<int SEQ, int WHICH>
__global__ void __launch_bounds__(256, 2) k_att(int layer, int nskip,
                      const float* __restrict__ qkv_w, const float* __restrict__ qkv_b,
                      const float* __restrict__ out_w, const float* __restrict__ out_b,
                      const float* __restrict__ ff_w,
                      const float* __restrict__ an_g, const float* __restrict__ an_b,
                      const float* __restrict__ sgp, const float* __restrict__ sbp){
  extern __shared__ float sm[];
  constexpr int QS = SEQ/4;
  float* s_qkv = sm;                    // [3][8][SEQ][8]
  float* s_un  = sm + 192*SEQ;          // union: xbuf[32][64] | {s_part[16][SEQ], s_ws8[8][SEQ]}
  float* s_part= s_un;
  float* s_ws8 = s_un + 16*SEQ;
  float* s_wv  = s_un + 24*SEQ;         // 64
  float* s_red = s_wv + 64;             // 288
  int b = blockIdx.x, tid = threadIdx.x;
  int lane = tid & 31, wrp = tid >> 5;
  const float* xsrc = (WHICH == 0) ? &g_cc[b][0][0] : &g_fbT[b][0][0][0];

  const float* QW = qkv_w + (size_t)(layer*2+WHICH)*12288;
  const float* QB = qkv_b + (layer*2+WHICH)*192;
  ull wreg2[32]; ull bias2 = 0ull; float* dst = s_qkv;
  if (tid < 192){
    int ty = tid / 64, c = tid % 64, h = c >> 3, kk = c & 7;
    const float* wp = QW + ty*4096 + c;
    #pragma unroll
    for (int i = 0; i < 32; i++) wreg2[i] = pack2(wp[(2*i)*64], wp[(2*i+1)*64]);
    bias2 = pack2(QB[ty*64 + c], 0.f);
    dst = s_qkv + ty*8*SEQ*8 + h*SEQ*8 + kk;
  }
  for (int ck = 0; ck < SEQ; ck += 32){
    int lim = (SEQ - ck >= 32) ? 32 : (SEQ - ck);   // 32 or 4 (SEQ=100 tail)
    for (int idx = tid; idx < 2048; idx += 256){
      int s = ck + (idx >> 6);
      if (s < SEQ) s_un[idx] = xsrc[s*64 + (idx & 63)];
    }
    __syncthreads();
    if (tid < 192){
      int half = lim >> 1;
      for (int i2 = 0; i2 < half; i2++){
        const ulonglong2* xrA = (const ulonglong2*)(s_un + i2*64);
        const ulonglong2* xrB = (const ulonglong2*)(s_un + (i2+half)*64);
        ull aA = bias2, aB = 0ull, bA = bias2, bB = 0ull;
        #pragma unroll
        for (int i = 0; i < 16; i++){
          ulonglong2 va = xrA[i];
          ulonglong2 vb = xrB[i];
          fma2(aA, va.x, wreg2[2*i]); fma2(aB, va.y, wreg2[2*i+1]);
          fma2(bA, vb.x, wreg2[2*i]); fma2(bB, vb.y, wreg2[2*i+1]);
        }
        dst[(ck + i2)*8]        = fsum2(aA) + fsum2(aB);
        dst[(ck + i2 + half)*8] = fsum2(bA) + fsum2(bB);
      }
    }
    __syncthreads();
  }

  float* s_q = s_qkv;
  float* s_k = s_qkv + 8*SEQ*8;
  float* s_v = s_qkv + 16*SEQ*8;
  const float scale = 0.3535533905932738f;

  for (int h = 0; h < 8; h++){
    {
      int r0 = tid >> 2, qd = tid & 3;
      for (int rb = 0; rb < SEQ; rb += 64){
        int r = rb + r0;
        bool valid = (r < SEQ);
        int rc = valid ? r : 0;
        const ulonglong2* qp = (const ulonglong2*)(s_q + (h*SEQ + rc)*8);
        ulonglong2 q01 = qp[0], q23 = qp[1];
        float rowv[QS];
        float mx = -1e30f;
        #pragma unroll
        for (int i = 0; i < QS; i++){
          int si = 4*i + qd;
          const ulonglong2* kp = (const ulonglong2*)(s_k + (h*SEQ + si)*8);
          ulonglong2 k01 = kp[0], k23 = kp[1];
          ull acc = 0ull;
          fma2(acc, q01.x, k01.x); fma2(acc, q01.y, k01.y);
          fma2(acc, q23.x, k23.x); fma2(acc, q23.y, k23.y);
          float a = fsum2(acc)*scale;
          rowv[i] = a; mx = fmaxf(mx, a);
        }
        mx = fmaxf(mx, __shfl_xor_sync(~0u, mx, 1));
        mx = fmaxf(mx, __shfl_xor_sync(~0u, mx, 2));
        float sum = 0.f;
        #pragma unroll
        for (int i = 0; i < QS; i++){ float e = __expf(rowv[i]-mx); rowv[i] = e; sum += e; }
        sum += __shfl_xor_sync(~0u, sum, 1);
        sum += __shfl_xor_sync(~0u, sum, 2);
        float inv = 1.f/sum;
        int slot = wrp + (rb >> 6)*8;
        #pragma unroll
        for (int i = 0; i < QS; i++){
          float pv = valid ? rowv[i]*inv : 0.f;
          pv += __shfl_xor_sync(~0u, pv, 4);
          pv += __shfl_xor_sync(~0u, pv, 8);
          pv += __shfl_xor_sync(~0u, pv, 16);
          if (lane < 4) s_part[slot*SEQ + 4*i + lane] = pv;
        }
      }
    }
    __syncthreads();
    if (tid < SEQ){
      float a = 0.f;
      #pragma unroll
      for (int w2 = 0; w2 < 16; w2++) a += s_part[w2*SEQ + tid];
      s_ws8[h*SEQ + tid] = a;
    }
    __syncthreads();
  }

  {
    int hk = tid >> 2, ch = tid & 3;
    int h2 = hk >> 3, kk2 = hk & 7;
    float acc = 0.f;
    for (int s = ch; s < SEQ; s += 4) acc += s_ws8[h2*SEQ + s] * s_v[(h2*SEQ + s)*8 + kk2];
    acc += __shfl_xor_sync(~0u, acc, 1);
    acc += __shfl_xor_sync(~0u, acc, 2);
    if (ch == 0) s_wv[hk] = acc;
  }
  __syncthreads();

  const float* OW = out_w + (size_t)(layer*2+WHICH)*4096;
  const float* OB = out_b + (layer*2+WHICH)*64;
  float part;
  {
    int hk = tid >> 2, ch = tid & 3;
    float acc = 0.f;
    #pragma unroll
    for (int d = 0; d < 16; d++) acc += OW[hk*64 + ch*16 + d];
    acc += __shfl_xor_sync(~0u, acc, 1);
    acc += __shfl_xor_sync(~0u, acc, 2);
    part = (ch == 0) ? s_wv[hk]*acc : 0.f;
    if (tid < 64) part += (float)SEQ * OB[tid];
  }
  { float w = wred32(part); if (lane == 0) s_red[wrp] = w; }
  __syncthreads();
  if (tid < 32){
    float v = (tid < 8) ? s_red[tid] : 0.f;
    v = wred32(v);
    if (tid == 0) s_red[64] = v;
  }
  __syncthreads();
  float s0 = s_red[64];
  __syncthreads();

  const float* W0 = ff_w + (size_t)((layer*2+WHICH)*2)*4096;
  const float* W1 = W0 + 4096;
  part = 0.f;
  for (int idx = tid; idx < 4096; idx += 256) part += fmaxf(s0*W0[idx], 0.f);
  { float w = wred32(part); if (lane == 0) s_red[wrp] = w; }
  __syncthreads();
  if (tid < 32){
    float v = (tid < 8) ? s_red[tid] : 0.f;
    v = wred32(v);
    if (tid == 0) s_red[64] = v;
  }
  __syncthreads();
  float s1 = s_red[64];

  {
    int p = tid >> 2, q = tid & 3;
    const float* G  = an_g + (layer*2+WHICH)*64;
    const float* Bb = an_b + (layer*2+WHICH)*64;
    const float* resid = WHICH ? &g_d0[b][0][0] : &g_last[b][0][0];
    float cur[16]; float sum = 0.f, sq = 0.f;
    #pragma unroll
    for (int c = 0; c < 16; c++){
      int d = q*16 + c;
      float v = s1*W1[p*64 + d] + resid[p*64 + d];
      cur[c] = v; sum += v; sq += v*v;
    }
    sum += __shfl_xor_sync(~0u, sum, 1); sum += __shfl_xor_sync(~0u, sum, 2);
    sq  += __shfl_xor_sync(~0u, sq , 1); sq  += __shfl_xor_sync(~0u, sq , 2);
    float mean = sum*(1.f/64.f);
    float var  = sq*(1.f/64.f) - mean*mean;
    float inv  = rsqrtf(var + EPSV);
    #pragma unroll
    for (int c = 0; c < 16; c++){
      int d = q*16 + c;
      cur[c] = (cur[c] - mean)*inv*G[d] + Bb[d];
    }
    if (WHICH == 0){
      #pragma unroll
      for (int c = 0; c < 16; c++){
        int d = q*16 + c;
        g_d0[b][p][d] = cur[c];
        g_d0T[b][d][p] = cur[c];
      }
    } else {
      #pragma unroll
      for (int c = 0; c < 16; c++){
        int d = q*16 + c;
        g_byp[layer][b][p][d] = cur[c];
      }
      for (int ss = 0; ss < nskip; ss++){
        int src = layer - (1 << ss) + 1;
        const float* Gs = sgp + (layer*4 + ss)*64;
        const float* Bs = sbp + (layer*4 + ss)*64;
        float sum2 = 0.f, sq2 = 0.f; float t[16];
        #pragma unroll
        for (int c = 0; c < 16; c++){
          int d = q*16 + c;
          float add = (src == layer) ? cur[c] : g_byp[src][b][p][d];
          float v = cur[c] + add;
          t[c] = v; sum2 += v; sq2 += v*v;
        }
        sum2 += __shfl_xor_sync(~0u, sum2, 1); sum2 += __shfl_xor_sync(~0u, sum2, 2);
        sq2  += __shfl_xor_sync(~0u, sq2 , 1); sq2  += __shfl_xor_sync(~0u, sq2 , 2);
        float m2 = sum2*(1.f/64.f);
        float v2 = sq2*(1.f/64.f) - m2*m2;
        float i2 = rsqrtf(v2 + EPSV);
        #pragma unroll
        for (int c = 0; c < 16; c++){
          int d = q*16 + c;
          cur[c] = (t[c] - m2)*i2*Gs[d] + Bs[d];
        }
      }
      #pragma unroll
      for (int c = 0; c < 16; c++){
        int d = q*16 + c;
        g_last[b][p][d] = cur[c];
      }
    }
  }
}

// ---------------- fused GRU (R13-verified) ----------------
__global__ void __launch_bounds__(192) k_gru(int layer,
                      const float* __restrict__ gk, const float* __restrict__ gr,
                      const float* __restrict__ gb){
  extern __shared__ float sg[];
  float* s_dT  = sg;
  float* s_hnT = sg;
  float* s_xg  = sg + 4224;
  float* s_h   = s_xg + 12288;
  float* s_hg  = s_h + 64;
  int blk = blockIdx.x, b = blk >> 1, dir = blk & 1;
  int j = threadIdx.x;
  for (int idx = j; idx < 4096; idx += 192) s_dT[idx] = (&g_d0T[b][0][0])[idx];
  const float* K = gk + (size_t)(layer*2+dir)*12288;
  const float* R = gr + (size_t)(layer*2+dir)*12288;
  ull bias2 = pack2(gb[((layer*2+dir)*2 + 0)*192 + j], 0.f);
  ull wr2[32];
  #pragma unroll
  for (int i = 0; i < 32; i++) wr2[i] = pack2(K[(2*i)*192 + j], K[(2*i+1)*192 + j]);
  if (j < 64) s_h[j] = g_mstate[b][layer][dir][j];
  __syncthreads();
  for (int t0 = 0; t0 < 64; t0 += 2){
    int tcA = dir ? (63 - t0) : t0;
    int tcB = dir ? (62 - t0) : (t0 + 1);
    const ulonglong2* xA = (const ulonglong2*)(s_dT + tcA*64);
    const ulonglong2* xB = (const ulonglong2*)(s_dT + tcB*64);
    ull aA = bias2, aB = 0ull, bA = bias2, bB = 0ull;
    #pragma unroll
    for (int i = 0; i < 16; i++){
      ulonglong2 va = xA[i];
      ulonglong2 vb = xB[i];
      fma2(aA, va.x, wr2[2*i]); fma2(aB, va.y, wr2[2*i+1]);
      fma2(bA, vb.x, wr2[2*i]); fma2(bB, vb.y, wr2[2*i+1]);
    }
    s_xg[t0*192 + j]     = fsum2(aA) + fsum2(aB);
    s_xg[(t0+1)*192 + j] = fsum2(bA) + fsum2(bB);
  }
  ull br2 = pack2(gb[((layer*2+dir)*2 + 1)*192 + j], 0.f);
  #pragma unroll
  for (int i = 0; i < 32; i++) wr2[i] = pack2(R[(2*i)*192 + j], R[(2*i+1)*192 + j]);
  __syncthreads();
  for (int t = 0; t < 64; t++){
    const ulonglong2* h4 = (const ulonglong2*)s_h;
    ull a0 = br2, a1 = 0ull, a2 = 0ull, a3 = 0ull;
    #pragma unroll
    for (int i = 0; i < 8; i++){
      ulonglong2 hv = h4[i];
      ulonglong2 hw = h4[i+8];
      fma2(a0, hv.x, wr2[2*i]);      fma2(a1, hv.y, wr2[2*i+1]);
      fma2(a2, hw.x, wr2[16+2*i]);   fma2(a3, hw.y, wr2[16+2*i+1]);
    }
    s_hg[j] = (fsum2(a0) + fsum2(a1)) + (fsum2(a2) + fsum2(a3));
    __syncthreads();
    if (j < 64){
      float xz = s_xg[t*192 + j], xr2 = s_xg[t*192 + 64 + j], xh = s_xg[t*192 + 128 + j];
      float z  = 1.f/(1.f + __expf(-(xz  + s_hg[j])));
      float rt = 1.f/(1.f + __expf(-(xr2 + s_hg[64 + j])));
      float c  = tanhf(xh + rt*s_hg[128 + j]);
      float hn = z*s_h[j] + (1.f - z)*c;
      s_h[j] = hn;
      s_hnT[j*65 + t] = hn;
    }
    __syncthreads();
  }
  for (int idx = j; idx < 4096; idx += 192){
    int f = idx >> 6, t2 = idx & 63;
    g_fbT[b][dir][f][t2] = s_hnT[f*65 + t2];
  }
  if (j < 64) g_states[b][layer][dir][j] = s_h[j];
}

__global__ void k_final(float* __restrict__ out){
  int b = blockIdx.x;
  float* o1 = out;
  float* o2 = out + (size_t)BN*5120;
  for (int idx = threadIdx.x; idx < 64*80; idx += blockDim.x){
    int p = idx/80, c = idx%80;
    float v;
    if (c < 64) v = g_last[b][p][c];
    else { int cc = c - 64; v = g_states[b][cc>>1][cc&1][p]; }
    o1[b*5120 + idx] = v;
  }
  for (int idx = threadIdx.x; idx < 1024; idx += blockDim.x){
    int cp = idx >> 6, f = idx & 63;
    o2[b*1024 + idx] = g_states[b][cp>>1][cp&1][f];
  }
}

extern "C" void kernel_launch(void* const* d_in, const int* in_sizes, int n_in,
                              void* d_out, int out_size){
  const float* x      = (const float*)d_in[0];
  const float* state  = (const float*)d_in[1];
  const float* conv_w4= (const float*)d_in[2];
  const float* conv_w3= (const float*)d_in[3];
  const float* conv_w2= (const float*)d_in[4];
  const float* conv_w1= (const float*)d_in[5];
  const float* conv_b = (const float*)d_in[6];
  const float* qkv_w  = (const float*)d_in[7];
  const float* qkv_b  = (const float*)d_in[8];
  const float* out_w  = (const float*)d_in[9];
  const float* out_b  = (const float*)d_in[10];
  const float* ff_w   = (const float*)d_in[11];
  const float* an_g   = (const float*)d_in[12];
  const float* an_b   = (const float*)d_in[13];
  const float* gru_k  = (const float*)d_in[14];
  const float* gru_r  = (const float*)d_in[15];
  const float* gru_b  = (const float*)d_in[16];
  const float* skip_g = (const float*)d_in[17];
  const float* skip_b = (const float*)d_in[18];

  int smem0 = (216*100 + 352) * 4;
  int smem1 = (216*128 + 352) * 4;
  int smemG = (4224 + 12288 + 64 + 192) * 4;
  static int attr_done = 0;
  if (!attr_done){
    cudaFuncSetAttribute(k_att<100,0>, cudaFuncAttributeMaxDynamicSharedMemorySize, smem0);
    cudaFuncSetAttribute(k_att<128,1>, cudaFuncAttributeMaxDynamicSharedMemorySize, smem1);
    cudaFuncSetAttribute(k_gru, cudaFuncAttributeMaxDynamicSharedMemorySize, smemG);
    attr_done = 1;
  }

  k_init<<<BN, 256>>>(x, state);
  for (int i = 0; i < LL; i++){
    int ns = 0;
    for (int j = 1; (i+1) % j == 0; j *= 2) ns++;
    k_conv<<<BN, 256>>>(i, conv_w4, conv_w3, conv_w2, conv_w1, conv_b);
    k_att<100,0><<<BN, 256, smem0>>>(i, 0, qkv_w, qkv_b, out_w, out_b, ff_w, an_g, an_b, skip_g, skip_b);
    k_gru<<<BN*2, 192, smemG>>>(i, gru_k, gru_r, gru_b);
    k_att<128,1><<<BN, 256, smem1>>>(i, ns, qkv_w, qkv_b, out_w, out_b, ff_w, an_g, an_b, skip_g, skip_b);
  }
  k_final<<<BN, 256>>>((float*)d_out);
}